// round 4
// baseline (speedup 1.0000x reference)
#include <cuda_runtime.h>
#include <cuda_bf16.h>
#include <math.h>

// Problem constants (fixed shapes for this problem instance)
constexpr int B_   = 2;
constexpr int T_   = 1024;
constexpr int C_   = 4096;
constexpr int HQ   = 32;
constexpr int HKV  = 8;
constexpr int D_   = 128;
constexpr int G_   = 4;      // HQ / HKV
constexpr int CT_  = 4096;   // cache T capacity

// Scratch (static device memory; no allocations)
__device__ float g_q  [(size_t)B_ * T_ * HQ  * D_];   // 33.5 MB
__device__ float g_k  [(size_t)B_ * T_ * HKV * D_];   //  8.4 MB
__device__ float g_v  [(size_t)B_ * T_ * HKV * D_];   //  8.4 MB
__device__ float g_ctx[(size_t)B_ * T_ * HQ  * D_];   // 33.5 MB

// ---------------------------------------------------------------------------
// GEMM: C[M,N] = A[M,K] * B[N,K]^T   (torch Linear layout; both K-contiguous)
// 128x128 tile, BK=16, 256 threads, 8x8 per thread (2x2 blocks of float4).
// ---------------------------------------------------------------------------
__global__ void __launch_bounds__(256) gemm_nt_kernel(
    const float* __restrict__ A, const float* __restrict__ Bm,
    float* __restrict__ C, int M, int N, int K) {
  __shared__ float As[16][128];
  __shared__ float Bs[16][128];

  const int tid = threadIdx.x;
  const int tx = tid & 15;        // 0..15 (col groups)
  const int ty = tid >> 4;        // 0..15 (row groups)
  const int bm = blockIdx.y << 7;
  const int bn = blockIdx.x << 7;

  const int lr = tid >> 2;        // 0..63
  const int lc = (tid & 3) << 2;  // 0,4,8,12

  float4 acc[8][2];
#pragma unroll
  for (int i = 0; i < 8; i++) {
    acc[i][0] = make_float4(0.f, 0.f, 0.f, 0.f);
    acc[i][1] = make_float4(0.f, 0.f, 0.f, 0.f);
  }

  for (int k0 = 0; k0 < K; k0 += 16) {
#pragma unroll
    for (int h = 0; h < 2; h++) {
      int r = lr + h * 64;
      float4 va = *(const float4*)(A  + (size_t)(bm + r) * K + k0 + lc);
      As[lc + 0][r] = va.x; As[lc + 1][r] = va.y;
      As[lc + 2][r] = va.z; As[lc + 3][r] = va.w;
      float4 vb = *(const float4*)(Bm + (size_t)(bn + r) * K + k0 + lc);
      Bs[lc + 0][r] = vb.x; Bs[lc + 1][r] = vb.y;
      Bs[lc + 2][r] = vb.z; Bs[lc + 3][r] = vb.w;
    }
    __syncthreads();

#pragma unroll
    for (int kk = 0; kk < 16; kk++) {
      float4 a0 = *(const float4*)&As[kk][(ty << 2)];
      float4 a1 = *(const float4*)&As[kk][(ty << 2) + 64];
      float4 b0 = *(const float4*)&Bs[kk][(tx << 2)];
      float4 b1 = *(const float4*)&Bs[kk][(tx << 2) + 64];
      float ra[8] = {a0.x, a0.y, a0.z, a0.w, a1.x, a1.y, a1.z, a1.w};
#pragma unroll
      for (int i = 0; i < 8; i++) {
        acc[i][0].x += ra[i] * b0.x; acc[i][0].y += ra[i] * b0.y;
        acc[i][0].z += ra[i] * b0.z; acc[i][0].w += ra[i] * b0.w;
        acc[i][1].x += ra[i] * b1.x; acc[i][1].y += ra[i] * b1.y;
        acc[i][1].z += ra[i] * b1.z; acc[i][1].w += ra[i] * b1.w;
      }
    }
    __syncthreads();
  }

#pragma unroll
  for (int i = 0; i < 8; i++) {
    int r = bm + (ty << 2) + (i < 4 ? i : 60 + i);  // i>=4 -> +64+(i-4)
    float* cp = C + (size_t)r * N + bn;
    *(float4*)(cp + (tx << 2))      = acc[i][0];
    *(float4*)(cp + (tx << 2) + 64) = acc[i][1];
  }
}

// ---------------------------------------------------------------------------
// RoPE over fresh q (B,T,HQ,D) and k (B,T,HKV,D), interleaved pairs (2i,2i+1)
// ---------------------------------------------------------------------------
__global__ void rope_kernel(float* __restrict__ q, float* __restrict__ k,
                            const int* __restrict__ spp) {
  const int sp = *spp;
  const int qpairs = B_ * T_ * HQ * (D_ / 2);
  const int kpairs = B_ * T_ * HKV * (D_ / 2);
  int idx = blockIdx.x * blockDim.x + threadIdx.x;
  float* base;
  int H;
  if (idx < qpairs) {
    base = q; H = HQ;
  } else {
    idx -= qpairs;
    if (idx >= kpairs) return;
    base = k; H = HKV;
  }
  const int i = idx & 63;             // pair index 0..63
  const int h = (idx >> 6) % H;
  const int m = idx / (64 * H);       // b*T + t
  const int t = m % T_;

  // inv_freq = 10000^(-i/64)
  const float freq = __expf(-(float)i * (9.210340371976184f / 64.f));
  const float ang  = (float)(sp + t) * freq;
  const double ad  = (double)ang;     // accurate range reduction
  const float c = (float)cos(ad);
  const float s = (float)sin(ad);

  size_t off = ((size_t)m * H + h) * D_ + (i << 1);
  float x1 = base[off], x2 = base[off + 1];
  base[off]     = x1 * c - x2 * s;
  base[off + 1] = x1 * s + x2 * c;
}

// ---------------------------------------------------------------------------
// Flash attention (fp32, online softmax).
// Block: 512 threads = 16 warps; handles 8 t-values x 4 g = 32 queries of one
// (b, kv_head). Each warp owns 2 queries (adjacent t, same g).
// K chunk (32 keys) stored d-major with XOR swizzle; V row-major.
// 48 KB static shared total.
// ---------------------------------------------------------------------------
__global__ void __launch_bounds__(512) attn_kernel(
    const float* __restrict__ qg, const float* __restrict__ knew,
    const float* __restrict__ vnew, const float* __restrict__ ck,
    const float* __restrict__ cv, const int* __restrict__ spp,
    float* __restrict__ ctx) {
  __shared__ float q_sh[32 * 128];
  __shared__ float Kt[32 * 128];
  __shared__ float Vs[32 * 128];

  const int sp = *spp;
  const int Stot = sp + T_;
  const int tid = threadIdx.x, lane = tid & 31, w = tid >> 5;
  const int blk = blockIdx.x;
  const int t0 = (blk & 127) << 3;     // T/8 = 128 t-tiles
  const int kv = (blk >> 7) & 7;
  const int b  = blk >> 10;

  // Load 32 query rows into shared (float4, coalesced)
  for (int idx = tid; idx < 1024; idx += 512) {
    int r = idx >> 5, dq = idx & 31;
    int t = t0 + (r >> 2), qh = kv * G_ + (r & 3);
    *(float4*)&q_sh[r * 128 + (dq << 2)] =
        *(const float4*)(qg + (((size_t)b * T_ + t) * HQ + qh) * D_ + (dq << 2));
  }

  const int g = w & 3, tp = w >> 2;
  const int tA = t0 + tp * 2, tB = tA + 1;
  const int rowA = tp * 8 + g, rowB = rowA + 4;

  float mA = -1e30f, mB = -1e30f, lA = 0.f, lB = 0.f;
  float4 accA = make_float4(0.f, 0.f, 0.f, 0.f);
  float4 accB = make_float4(0.f, 0.f, 0.f, 0.f);
  const float scale = 0.08838834764831845f;  // 1/sqrt(128)

  const int smax = sp + t0 + 7;  // last visible key for this block
  for (int s0 = 0; s0 <= smax; s0 += 32) {
    __syncthreads();
    // Load K/V chunk: 32 keys x 128 d (float4, coalesced; cache vs fresh)
    for (int idx = tid; idx < 1024; idx += 512) {
      int j = idx >> 5, dq = idx & 31;
      int s = s0 + j;
      float4 kx = make_float4(0.f, 0.f, 0.f, 0.f), vx = kx;
      if (s < Stot) {
        size_t off;
        const float *kp, *vp;
        if (s < sp) {
          off = (((size_t)b * CT_ + s) * HKV + kv) * (size_t)D_ + (dq << 2);
          kp = ck; vp = cv;
        } else {
          off = (((size_t)b * T_ + (s - sp)) * HKV + kv) * (size_t)D_ + (dq << 2);
          kp = knew; vp = vnew;
        }
        kx = *(const float4*)(kp + off);
        vx = *(const float4*)(vp + off);
      }
      *(float4*)&Kt[dq * 128 + ((j ^ (dq & 7)) << 2)] = kx;  // swizzled store
      *(float4*)&Vs[j * 128 + (dq << 2)] = vx;
    }
    __syncthreads();

    if (s0 > sp + tB) continue;  // fully masked for this warp's queries

    // Scores: lane 'lane' owns key j=lane
    float scA = 0.f, scB = 0.f;
#pragma unroll 8
    for (int dq = 0; dq < 32; dq++) {
      float4 kf = *(const float4*)&Kt[dq * 128 + ((lane ^ (dq & 7)) << 2)];
      float4 qa = *(const float4*)&q_sh[rowA * 128 + (dq << 2)];
      float4 qb = *(const float4*)&q_sh[rowB * 128 + (dq << 2)];
      scA += qa.x * kf.x + qa.y * kf.y + qa.z * kf.z + qa.w * kf.w;
      scB += qb.x * kf.x + qb.y * kf.y + qb.z * kf.z + qb.w * kf.w;
    }
    scA *= scale; scB *= scale;
    int s = s0 + lane;
    if (s > sp + tA) scA = -1e30f;
    if (s > sp + tB) scB = -1e30f;

    // Online softmax update
    float cmA = scA, cmB = scB;
#pragma unroll
    for (int o = 16; o; o >>= 1) {
      cmA = fmaxf(cmA, __shfl_xor_sync(0xffffffffu, cmA, o));
      cmB = fmaxf(cmB, __shfl_xor_sync(0xffffffffu, cmB, o));
    }
    float mnA = fmaxf(mA, cmA), mnB = fmaxf(mB, cmB);
    float sclA = __expf(mA - mnA), sclB = __expf(mB - mnB);
    float pA = __expf(scA - mnA), pB = __expf(scB - mnB);
    mA = mnA; mB = mnB;
    float psA = pA, psB = pB;
#pragma unroll
    for (int o = 16; o; o >>= 1) {
      psA += __shfl_xor_sync(0xffffffffu, psA, o);
      psB += __shfl_xor_sync(0xffffffffu, psB, o);
    }
    lA = lA * sclA + psA;
    lB = lB * sclB + psB;
    accA.x *= sclA; accA.y *= sclA; accA.z *= sclA; accA.w *= sclA;
    accB.x *= sclB; accB.y *= sclB; accB.z *= sclB; accB.w *= sclB;

    // P @ V : lane owns d = lane*4 .. lane*4+3
#pragma unroll 8
    for (int j = 0; j < 32; j++) {
      float4 v = *(const float4*)&Vs[j * 128 + (lane << 2)];
      float pa = __shfl_sync(0xffffffffu, pA, j);
      float pb = __shfl_sync(0xffffffffu, pB, j);
      accA.x += pa * v.x; accA.y += pa * v.y; accA.z += pa * v.z; accA.w += pa * v.w;
      accB.x += pb * v.x; accB.y += pb * v.y; accB.z += pb * v.z; accB.w += pb * v.w;
    }
  }

  float iA = 1.f / lA, iB = 1.f / lB;
  accA.x *= iA; accA.y *= iA; accA.z *= iA; accA.w *= iA;
  accB.x *= iB; accB.y *= iB; accB.z *= iB; accB.w *= iB;
  size_t oA = (((size_t)b * T_ + tA) * HQ + kv * G_ + g) * (size_t)D_ + (lane << 2);
  size_t oB = (((size_t)b * T_ + tB) * HQ + kv * G_ + g) * (size_t)D_ + (lane << 2);
  *(float4*)(ctx + oA) = accA;
  *(float4*)(ctx + oB) = accB;
}

// ---------------------------------------------------------------------------
// kernel_launch: q/k/v proj -> rope -> flash attention -> o proj
// ---------------------------------------------------------------------------
extern "C" void kernel_launch(void* const* d_in, const int* in_sizes, int n_in,
                              void* d_out, int out_size) {
  const float* x  = (const float*)d_in[0];
  const int*   sp = (const int*)  d_in[1];
  const float* ck = (const float*)d_in[2];
  const float* cv = (const float*)d_in[3];
  const float* Wq = (const float*)d_in[4];
  const float* Wk = (const float*)d_in[5];
  const float* Wv = (const float*)d_in[6];
  const float* Wo = (const float*)d_in[7];
  float* out = (float*)d_out;

  static float *qb = nullptr, *kb = nullptr, *vb = nullptr, *cb = nullptr;
  if (!qb) {
    cudaGetSymbolAddress((void**)&qb, g_q);
    cudaGetSymbolAddress((void**)&kb, g_k);
    cudaGetSymbolAddress((void**)&vb, g_v);
    cudaGetSymbolAddress((void**)&cb, g_ctx);
  }

  const int M = B_ * T_;  // 2048

  // QKV projections
  gemm_nt_kernel<<<dim3(C_ / 128, M / 128), 256>>>(x, Wq, qb, M, C_, C_);
  gemm_nt_kernel<<<dim3((HKV * D_) / 128, M / 128), 256>>>(x, Wk, kb, M, HKV * D_, C_);
  gemm_nt_kernel<<<dim3((HKV * D_) / 128, M / 128), 256>>>(x, Wv, vb, M, HKV * D_, C_);

  // RoPE on fresh q and k
  const int totalpairs = M * HQ * (D_ / 2) + M * HKV * (D_ / 2);
  rope_kernel<<<(totalpairs + 255) / 256, 256>>>(qb, kb, sp);

  // Attention: 2 * 8 * (1024/8) = 2048 blocks
  attn_kernel<<<B_ * HKV * (T_ / 8), 512>>>(qb, kb, vb, ck, cv, sp, cb);

  // Output projection
  gemm_nt_kernel<<<dim3(C_ / 128, M / 128), 256>>>(cb, Wo, out, M, C_, C_);
}

// round 9
// speedup vs baseline: 1.6209x; 1.6209x over previous
#include <cuda_runtime.h>
#include <cuda_bf16.h>
#include <cstdint>
#include <math.h>

// Problem constants
constexpr int B_   = 2;
constexpr int T_   = 1024;
constexpr int C_   = 4096;
constexpr int HQ   = 32;
constexpr int HKV  = 8;
constexpr int D_   = 128;
constexpr int G_   = 4;
constexpr int CT_  = 4096;

// fp32 scratch
__device__ float g_q  [(size_t)B_ * T_ * HQ  * D_];
__device__ float g_k  [(size_t)B_ * T_ * HKV * D_];
__device__ float g_v  [(size_t)B_ * T_ * HKV * D_];
__device__ float g_ctx[(size_t)B_ * T_ * HQ  * D_];

// bf16 hi/lo scratch for tensor-core GEMMs
__device__ __nv_bfloat16 g_xh [(size_t)B_ * T_ * C_];
__device__ __nv_bfloat16 g_xl [(size_t)B_ * T_ * C_];
__device__ __nv_bfloat16 g_wqh[(size_t)C_ * C_];
__device__ __nv_bfloat16 g_wql[(size_t)C_ * C_];
__device__ __nv_bfloat16 g_wkh[(size_t)HKV * D_ * C_];
__device__ __nv_bfloat16 g_wkl[(size_t)HKV * D_ * C_];
__device__ __nv_bfloat16 g_wvh[(size_t)HKV * D_ * C_];
__device__ __nv_bfloat16 g_wvl[(size_t)HKV * D_ * C_];
__device__ __nv_bfloat16 g_woh[(size_t)C_ * C_];
__device__ __nv_bfloat16 g_wol[(size_t)C_ * C_];
__device__ __nv_bfloat16 g_cth[(size_t)B_ * T_ * C_];
__device__ __nv_bfloat16 g_ctl[(size_t)B_ * T_ * C_];

__device__ __forceinline__ uint32_t smem_u32(const void* p) {
  uint32_t a;
  asm("{ .reg .u64 t; cvta.to.shared.u64 t, %1; cvt.u32.u64 %0, t; }"
      : "=r"(a) : "l"(p));
  return a;
}

__device__ __forceinline__ void ldsm4(uint32_t* r, uint32_t addr) {
  asm volatile("ldmatrix.sync.aligned.m8n8.x4.shared.b16 {%0,%1,%2,%3}, [%4];"
               : "=r"(r[0]), "=r"(r[1]), "=r"(r[2]), "=r"(r[3]) : "r"(addr));
}

__device__ __forceinline__ void mma16816(float* d, const uint32_t* a,
                                         uint32_t b0, uint32_t b1) {
  asm volatile(
      "mma.sync.aligned.m16n8k16.row.col.f32.bf16.bf16.f32 "
      "{%0,%1,%2,%3},{%4,%5,%6,%7},{%8,%9},{%0,%1,%2,%3};"
      : "+f"(d[0]), "+f"(d[1]), "+f"(d[2]), "+f"(d[3])
      : "r"(a[0]), "r"(a[1]), "r"(a[2]), "r"(a[3]), "r"(b0), "r"(b1));
}

__device__ __forceinline__ void cp_async16(uint32_t dst, const void* src) {
  asm volatile("cp.async.cg.shared.global [%0], [%1], 16;"
               :: "r"(dst), "l"(src) : "memory");
}

// ---------------------------------------------------------------------------
// fp32 -> bf16 hi/lo split (elementwise, float4-vectorized)
// ---------------------------------------------------------------------------
__global__ void cvt_kernel(const float4* __restrict__ in,
                           __nv_bfloat162* __restrict__ hi,
                           __nv_bfloat162* __restrict__ lo, int n4) {
  int i = blockIdx.x * blockDim.x + threadIdx.x;
  if (i >= n4) return;
  float4 v = in[i];
  __nv_bfloat162 h0 = __float22bfloat162_rn(make_float2(v.x, v.y));
  __nv_bfloat162 h1 = __float22bfloat162_rn(make_float2(v.z, v.w));
  __nv_bfloat162 l0 = __float22bfloat162_rn(make_float2(
      v.x - __bfloat162float(h0.x), v.y - __bfloat162float(h0.y)));
  __nv_bfloat162 l1 = __float22bfloat162_rn(make_float2(
      v.z - __bfloat162float(h1.x), v.w - __bfloat162float(h1.y)));
  hi[2 * i] = h0; hi[2 * i + 1] = h1;
  lo[2 * i] = l0; lo[2 * i + 1] = l1;
}

// ---------------------------------------------------------------------------
// Tensor-core GEMM: C[M,N] = A[M,K] * B[N,K]^T, bf16 hi/lo inputs, fp32 out.
// 3-term split: Ah*Bh + Ah*Bl + Al*Bh. 128x128 tile, BK=64, 256 threads,
// 8 warps (2x4), warp tile 64x32. cp.async double-buffered smem, SW128
// swizzle, ldmatrix fragments, mma.sync.m16n8k16.
// Dynamic smem: 2 buffers x (Ah,Al,Bh,Bl) x 16KB = 128KB.
// ---------------------------------------------------------------------------
__global__ void __launch_bounds__(256) gemm_mma_kernel(
    const __nv_bfloat16* __restrict__ Ah, const __nv_bfloat16* __restrict__ Al,
    const __nv_bfloat16* __restrict__ Bh, const __nv_bfloat16* __restrict__ Bl,
    float* __restrict__ C, int M, int N, int K) {
  extern __shared__ char sm[];
  const int tid = threadIdx.x, lane = tid & 31, wid = tid >> 5;
  const int bm = blockIdx.y << 7, bn = blockIdx.x << 7;
  const uint32_t sbase = smem_u32(sm);

  const int warp_m = wid >> 2;   // 0..1
  const int warp_n = wid & 3;    // 0..3

  const __nv_bfloat16* srcs[4] = {Ah, Al, Bh, Bl};

  // cp.async loader: per chunk, 4 matrices of 128 rows x 128B
  auto issue = [&](int c, int buf) {
    const int k0 = c << 6;
    const int r = tid >> 1;            // 0..127
    const int s0 = (tid & 1) << 2;     // 0 or 4
#pragma unroll
    for (int m = 0; m < 4; m++) {
      const __nv_bfloat16* g =
          srcs[m] + (size_t)((m < 2 ? bm : bn) + r) * K + k0;
      uint32_t dstb = sbase + buf * 65536 + m * 16384 + r * 128;
      uint32_t rsw = (uint32_t)(r & 7) << 4;
#pragma unroll
      for (int i = 0; i < 4; i++) {
        int seg = s0 + i;
        cp_async16(dstb + ((uint32_t)(seg << 4) ^ rsw), g + seg * 8);
      }
    }
    asm volatile("cp.async.commit_group;" ::: "memory");
  };

  float acc[4][4][4];
#pragma unroll
  for (int i = 0; i < 4; i++)
#pragma unroll
    for (int j = 0; j < 4; j++)
#pragma unroll
      for (int t = 0; t < 4; t++) acc[i][j][t] = 0.f;

  const int l7 = lane & 7, m1b = (lane >> 3) & 1, m2b = lane >> 4;

  const int nch = K >> 6;
  issue(0, 0);
  for (int c = 0; c < nch; c++) {
    const int buf = c & 1;
    if (c + 1 < nch) {
      issue(c + 1, buf ^ 1);
      asm volatile("cp.async.wait_group 1;" ::: "memory");
    } else {
      asm volatile("cp.async.wait_group 0;" ::: "memory");
    }
    __syncthreads();

    const uint32_t bAh = sbase + buf * 65536;
    const uint32_t bAl = bAh + 16384;
    const uint32_t bBh = bAh + 32768;
    const uint32_t bBl = bAh + 49152;

#pragma unroll
    for (int kk = 0; kk < 4; kk++) {
      uint32_t ah[4][4], al[4][4], bh[2][4], bl[2][4];
#pragma unroll
      for (int i = 0; i < 4; i++) {
        int row = warp_m * 64 + i * 16 + l7 + m1b * 8;
        uint32_t bo = (uint32_t)(kk * 32 + m2b * 16) ^ ((uint32_t)(row & 7) << 4);
        uint32_t ro = (uint32_t)row * 128 + bo;
        ldsm4(ah[i], bAh + ro);
        ldsm4(al[i], bAl + ro);
      }
#pragma unroll
      for (int jp = 0; jp < 2; jp++) {
        int row = warp_n * 32 + jp * 16 + l7 + m2b * 8;
        uint32_t bo = (uint32_t)(kk * 32 + m1b * 16) ^ ((uint32_t)(row & 7) << 4);
        uint32_t ro = (uint32_t)row * 128 + bo;
        ldsm4(bh[jp], bBh + ro);
        ldsm4(bl[jp], bBl + ro);
      }
#pragma unroll
      for (int i = 0; i < 4; i++) {
#pragma unroll
        for (int j = 0; j < 4; j++) {
          uint32_t h0 = bh[j >> 1][(j & 1) * 2], h1 = bh[j >> 1][(j & 1) * 2 + 1];
          uint32_t l0 = bl[j >> 1][(j & 1) * 2], l1 = bl[j >> 1][(j & 1) * 2 + 1];
          mma16816(acc[i][j], ah[i], h0, h1);
          mma16816(acc[i][j], ah[i], l0, l1);
          mma16816(acc[i][j], al[i], h0, h1);
        }
      }
    }
    __syncthreads();
  }

  // Epilogue: fragment layout -> C
  const int rq = lane >> 2, cq = (lane & 3) << 1;
#pragma unroll
  for (int i = 0; i < 4; i++) {
#pragma unroll
    for (int j = 0; j < 4; j++) {
      int row0 = bm + warp_m * 64 + i * 16 + rq;
      int col = bn + warp_n * 32 + j * 8 + cq;
      *(float2*)(C + (size_t)row0 * N + col) =
          make_float2(acc[i][j][0], acc[i][j][1]);
      *(float2*)(C + (size_t)(row0 + 8) * N + col) =
          make_float2(acc[i][j][2], acc[i][j][3]);
    }
  }
}

// ---------------------------------------------------------------------------
// RoPE (fp32 sincosf)
// ---------------------------------------------------------------------------
__global__ void rope_kernel(float* __restrict__ q, float* __restrict__ k,
                            const int* __restrict__ spp) {
  const int sp = *spp;
  const int qpairs = B_ * T_ * HQ * (D_ / 2);
  const int kpairs = B_ * T_ * HKV * (D_ / 2);
  int idx = blockIdx.x * blockDim.x + threadIdx.x;
  float* base;
  int H;
  if (idx < qpairs) {
    base = q; H = HQ;
  } else {
    idx -= qpairs;
    if (idx >= kpairs) return;
    base = k; H = HKV;
  }
  const int i = idx & 63;
  const int h = (idx >> 6) % H;
  const int m = idx / (64 * H);
  const int t = m % T_;

  const float freq = __expf(-(float)i * (9.210340371976184f / 64.f));
  const float ang  = (float)(sp + t) * freq;
  float s, c;
  sincosf(ang, &s, &c);

  size_t off = ((size_t)m * H + h) * D_ + (i << 1);
  float x1 = base[off], x2 = base[off + 1];
  base[off]     = x1 * c - x2 * s;
  base[off + 1] = x1 * s + x2 * c;
}

// ---------------------------------------------------------------------------
// Flash attention (fp32, online softmax) — unchanged (verified).
// ---------------------------------------------------------------------------
__global__ void __launch_bounds__(512) attn_kernel(
    const float* __restrict__ qg, const float* __restrict__ knew,
    const float* __restrict__ vnew, const float* __restrict__ ck,
    const float* __restrict__ cv, const int* __restrict__ spp,
    float* __restrict__ ctx) {
  __shared__ float q_sh[32 * 128];
  __shared__ float Kt[32 * 128];
  __shared__ float Vs[32 * 128];

  const int sp = *spp;
  const int Stot = sp + T_;
  const int tid = threadIdx.x, lane = tid & 31, w = tid >> 5;
  const int blk = blockIdx.x;
  const int t0 = (blk & 127) << 3;
  const int kv = (blk >> 7) & 7;
  const int b  = blk >> 10;

  for (int idx = tid; idx < 1024; idx += 512) {
    int r = idx >> 5, dq = idx & 31;
    int t = t0 + (r >> 2), qh = kv * G_ + (r & 3);
    *(float4*)&q_sh[r * 128 + (dq << 2)] =
        *(const float4*)(qg + (((size_t)b * T_ + t) * HQ + qh) * D_ + (dq << 2));
  }

  const int g = w & 3, tp = w >> 2;
  const int tA = t0 + tp * 2, tB = tA + 1;
  const int rowA = tp * 8 + g, rowB = rowA + 4;

  float mA = -1e30f, mB = -1e30f, lA = 0.f, lB = 0.f;
  float4 accA = make_float4(0.f, 0.f, 0.f, 0.f);
  float4 accB = make_float4(0.f, 0.f, 0.f, 0.f);
  const float scale = 0.08838834764831845f;

  const int smax = sp + t0 + 7;
  for (int s0 = 0; s0 <= smax; s0 += 32) {
    __syncthreads();
    for (int idx = tid; idx < 1024; idx += 512) {
      int j = idx >> 5, dq = idx & 31;
      int s = s0 + j;
      float4 kx = make_float4(0.f, 0.f, 0.f, 0.f), vx = kx;
      if (s < Stot) {
        size_t off;
        const float *kp, *vp;
        if (s < sp) {
          off = (((size_t)b * CT_ + s) * HKV + kv) * (size_t)D_ + (dq << 2);
          kp = ck; vp = cv;
        } else {
          off = (((size_t)b * T_ + (s - sp)) * HKV + kv) * (size_t)D_ + (dq << 2);
          kp = knew; vp = vnew;
        }
        kx = *(const float4*)(kp + off);
        vx = *(const float4*)(vp + off);
      }
      *(float4*)&Kt[dq * 128 + ((j ^ (dq & 7)) << 2)] = kx;
      *(float4*)&Vs[j * 128 + (dq << 2)] = vx;
    }
    __syncthreads();

    if (s0 > sp + tB) continue;

    float scA = 0.f, scB = 0.f;
#pragma unroll 8
    for (int dq = 0; dq < 32; dq++) {
      float4 kf = *(const float4*)&Kt[dq * 128 + ((lane ^ (dq & 7)) << 2)];
      float4 qa = *(const float4*)&q_sh[rowA * 128 + (dq << 2)];
      float4 qb = *(const float4*)&q_sh[rowB * 128 + (dq << 2)];
      scA += qa.x * kf.x + qa.y * kf.y + qa.z * kf.z + qa.w * kf.w;
      scB += qb.x * kf.x + qb.y * kf.y + qb.z * kf.z + qb.w * kf.w;
    }
    scA *= scale; scB *= scale;
    int s = s0 + lane;
    if (s > sp + tA) scA = -1e30f;
    if (s > sp + tB) scB = -1e30f;

    float cmA = scA, cmB = scB;
#pragma unroll
    for (int o = 16; o; o >>= 1) {
      cmA = fmaxf(cmA, __shfl_xor_sync(0xffffffffu, cmA, o));
      cmB = fmaxf(cmB, __shfl_xor_sync(0xffffffffu, cmB, o));
    }
    float mnA = fmaxf(mA, cmA), mnB = fmaxf(mB, cmB);
    float sclA = __expf(mA - mnA), sclB = __expf(mB - mnB);
    float pA = __expf(scA - mnA), pB = __expf(scB - mnB);
    mA = mnA; mB = mnB;
    float psA = pA, psB = pB;
#pragma unroll
    for (int o = 16; o; o >>= 1) {
      psA += __shfl_xor_sync(0xffffffffu, psA, o);
      psB += __shfl_xor_sync(0xffffffffu, psB, o);
    }
    lA = lA * sclA + psA;
    lB = lB * sclB + psB;
    accA.x *= sclA; accA.y *= sclA; accA.z *= sclA; accA.w *= sclA;
    accB.x *= sclB; accB.y *= sclB; accB.z *= sclB; accB.w *= sclB;

#pragma unroll 8
    for (int j = 0; j < 32; j++) {
      float4 v = *(const float4*)&Vs[j * 128 + (lane << 2)];
      float pa = __shfl_sync(0xffffffffu, pA, j);
      float pb = __shfl_sync(0xffffffffu, pB, j);
      accA.x += pa * v.x; accA.y += pa * v.y; accA.z += pa * v.z; accA.w += pa * v.w;
      accB.x += pb * v.x; accB.y += pb * v.y; accB.z += pb * v.z; accB.w += pb * v.w;
    }
  }

  float iA = 1.f / lA, iB = 1.f / lB;
  accA.x *= iA; accA.y *= iA; accA.z *= iA; accA.w *= iA;
  accB.x *= iB; accB.y *= iB; accB.z *= iB; accB.w *= iB;
  size_t oA = (((size_t)b * T_ + tA) * HQ + kv * G_ + g) * (size_t)D_ + (lane << 2);
  size_t oB = (((size_t)b * T_ + tB) * HQ + kv * G_ + g) * (size_t)D_ + (lane << 2);
  *(float4*)(ctx + oA) = accA;
  *(float4*)(ctx + oB) = accB;
}

// ---------------------------------------------------------------------------
// kernel_launch
// ---------------------------------------------------------------------------
extern "C" void kernel_launch(void* const* d_in, const int* in_sizes, int n_in,
                              void* d_out, int out_size) {
  const float* x  = (const float*)d_in[0];
  const int*   sp = (const int*)  d_in[1];
  const float* ck = (const float*)d_in[2];
  const float* cv = (const float*)d_in[3];
  const float* Wq = (const float*)d_in[4];
  const float* Wk = (const float*)d_in[5];
  const float* Wv = (const float*)d_in[6];
  const float* Wo = (const float*)d_in[7];
  float* out = (float*)d_out;

  constexpr int DYN_SMEM = 131072;

  static float *qb, *kb, *vb, *cb;
  static __nv_bfloat16 *xh, *xl, *wqh, *wql, *wkh, *wkl, *wvh, *wvl, *woh, *wol,
      *cth, *ctl;
  static bool init_done = false;
  if (!init_done) {
    cudaGetSymbolAddress((void**)&qb, g_q);
    cudaGetSymbolAddress((void**)&kb, g_k);
    cudaGetSymbolAddress((void**)&vb, g_v);
    cudaGetSymbolAddress((void**)&cb, g_ctx);
    cudaGetSymbolAddress((void**)&xh, g_xh);
    cudaGetSymbolAddress((void**)&xl, g_xl);
    cudaGetSymbolAddress((void**)&wqh, g_wqh);
    cudaGetSymbolAddress((void**)&wql, g_wql);
    cudaGetSymbolAddress((void**)&wkh, g_wkh);
    cudaGetSymbolAddress((void**)&wkl, g_wkl);
    cudaGetSymbolAddress((void**)&wvh, g_wvh);
    cudaGetSymbolAddress((void**)&wvl, g_wvl);
    cudaGetSymbolAddress((void**)&woh, g_woh);
    cudaGetSymbolAddress((void**)&wol, g_wol);
    cudaGetSymbolAddress((void**)&cth, g_cth);
    cudaGetSymbolAddress((void**)&ctl, g_ctl);
    cudaFuncSetAttribute(gemm_mma_kernel,
                         cudaFuncAttributeMaxDynamicSharedMemorySize, DYN_SMEM);
    init_done = true;
  }

  const int M = B_ * T_;  // 2048

  // fp32 -> bf16 hi/lo conversions
  const int n4x = M * C_ / 4;
  const int n4q = C_ * C_ / 4;
  const int n4k = HKV * D_ * C_ / 4;
  cvt_kernel<<<(n4x + 255) / 256, 256>>>((const float4*)x,
      (__nv_bfloat162*)xh, (__nv_bfloat162*)xl, n4x);
  cvt_kernel<<<(n4q + 255) / 256, 256>>>((const float4*)Wq,
      (__nv_bfloat162*)wqh, (__nv_bfloat162*)wql, n4q);
  cvt_kernel<<<(n4k + 255) / 256, 256>>>((const float4*)Wk,
      (__nv_bfloat162*)wkh, (__nv_bfloat162*)wkl, n4k);
  cvt_kernel<<<(n4k + 255) / 256, 256>>>((const float4*)Wv,
      (__nv_bfloat162*)wvh, (__nv_bfloat162*)wvl, n4k);
  cvt_kernel<<<(n4q + 255) / 256, 256>>>((const float4*)Wo,
      (__nv_bfloat162*)woh, (__nv_bfloat162*)wol, n4q);

  // QKV projections (tensor cores)
  gemm_mma_kernel<<<dim3(C_ / 128, M / 128), 256, DYN_SMEM>>>(
      xh, xl, wqh, wql, qb, M, C_, C_);
  gemm_mma_kernel<<<dim3((HKV * D_) / 128, M / 128), 256, DYN_SMEM>>>(
      xh, xl, wkh, wkl, kb, M, HKV * D_, C_);
  gemm_mma_kernel<<<dim3((HKV * D_) / 128, M / 128), 256, DYN_SMEM>>>(
      xh, xl, wvh, wvl, vb, M, HKV * D_, C_);

  // RoPE
  const int totalpairs = M * HQ * (D_ / 2) + M * HKV * (D_ / 2);
  rope_kernel<<<(totalpairs + 255) / 256, 256>>>(qb, kb, sp);

  // Attention
  attn_kernel<<<B_ * HKV * (T_ / 8), 512>>>(qb, kb, vb, ck, cv, sp, cb);

  // ctx -> bf16 hi/lo, then output projection
  cvt_kernel<<<(n4x + 255) / 256, 256>>>((const float4*)cb,
      (__nv_bfloat162*)cth, (__nv_bfloat162*)ctl, n4x);
  gemm_mma_kernel<<<dim3(C_ / 128, M / 128), 256, DYN_SMEM>>>(
      cth, ctl, woh, wol, out, M, C_, C_);
}

// round 10
// speedup vs baseline: 3.3885x; 2.0905x over previous
#include <cuda_runtime.h>
#include <cuda_bf16.h>
#include <cstdint>
#include <math.h>

// Problem constants
constexpr int B_   = 2;
constexpr int T_   = 1024;
constexpr int C_   = 4096;
constexpr int HQ   = 32;
constexpr int HKV  = 8;
constexpr int D_   = 128;
constexpr int G_   = 4;
constexpr int CT_  = 4096;

// fp32 scratch
__device__ float g_q  [(size_t)B_ * T_ * HQ  * D_];
__device__ float g_k  [(size_t)B_ * T_ * HKV * D_];
__device__ float g_v  [(size_t)B_ * T_ * HKV * D_];
__device__ float g_ctx[(size_t)B_ * T_ * HQ  * D_];

// bf16 hi/lo scratch for tensor-core GEMMs
__device__ __nv_bfloat16 g_xh [(size_t)B_ * T_ * C_];
__device__ __nv_bfloat16 g_xl [(size_t)B_ * T_ * C_];
__device__ __nv_bfloat16 g_wqh[(size_t)C_ * C_];
__device__ __nv_bfloat16 g_wql[(size_t)C_ * C_];
__device__ __nv_bfloat16 g_wkh[(size_t)HKV * D_ * C_];
__device__ __nv_bfloat16 g_wkl[(size_t)HKV * D_ * C_];
__device__ __nv_bfloat16 g_wvh[(size_t)HKV * D_ * C_];
__device__ __nv_bfloat16 g_wvl[(size_t)HKV * D_ * C_];
__device__ __nv_bfloat16 g_woh[(size_t)C_ * C_];
__device__ __nv_bfloat16 g_wol[(size_t)C_ * C_];
__device__ __nv_bfloat16 g_cth[(size_t)B_ * T_ * C_];
__device__ __nv_bfloat16 g_ctl[(size_t)B_ * T_ * C_];

// bf16 hi/lo attention operands
__device__ __nv_bfloat16 g_qah[(size_t)B_ * T_ * HQ * D_];
__device__ __nv_bfloat16 g_qal[(size_t)B_ * T_ * HQ * D_];
__device__ __nv_bfloat16 g_kch[(size_t)B_ * CT_ * HKV * D_];
__device__ __nv_bfloat16 g_kcl[(size_t)B_ * CT_ * HKV * D_];
__device__ __nv_bfloat16 g_vch[(size_t)B_ * CT_ * HKV * D_];
__device__ __nv_bfloat16 g_vcl[(size_t)B_ * CT_ * HKV * D_];

__device__ __forceinline__ uint32_t smem_u32(const void* p) {
  uint32_t a;
  asm("{ .reg .u64 t; cvta.to.shared.u64 t, %1; cvt.u32.u64 %0, t; }"
      : "=r"(a) : "l"(p));
  return a;
}

__device__ __forceinline__ void ldsm4(uint32_t* r, uint32_t addr) {
  asm volatile("ldmatrix.sync.aligned.m8n8.x4.shared.b16 {%0,%1,%2,%3}, [%4];"
               : "=r"(r[0]), "=r"(r[1]), "=r"(r[2]), "=r"(r[3]) : "r"(addr));
}

__device__ __forceinline__ void ldsm4t(uint32_t* r, uint32_t addr) {
  asm volatile("ldmatrix.sync.aligned.m8n8.x4.trans.shared.b16 {%0,%1,%2,%3}, [%4];"
               : "=r"(r[0]), "=r"(r[1]), "=r"(r[2]), "=r"(r[3]) : "r"(addr));
}

__device__ __forceinline__ void mma16816(float* d, const uint32_t* a,
                                         uint32_t b0, uint32_t b1) {
  asm volatile(
      "mma.sync.aligned.m16n8k16.row.col.f32.bf16.bf16.f32 "
      "{%0,%1,%2,%3},{%4,%5,%6,%7},{%8,%9},{%0,%1,%2,%3};"
      : "+f"(d[0]), "+f"(d[1]), "+f"(d[2]), "+f"(d[3])
      : "r"(a[0]), "r"(a[1]), "r"(a[2]), "r"(a[3]), "r"(b0), "r"(b1));
}

__device__ __forceinline__ void cp_async16(uint32_t dst, const void* src) {
  asm volatile("cp.async.cg.shared.global [%0], [%1], 16;"
               :: "r"(dst), "l"(src) : "memory");
}

// ---------------------------------------------------------------------------
// fp32 -> bf16 hi/lo split (elementwise)
// ---------------------------------------------------------------------------
__global__ void cvt_kernel(const float4* __restrict__ in,
                           __nv_bfloat162* __restrict__ hi,
                           __nv_bfloat162* __restrict__ lo, int n4) {
  int i = blockIdx.x * blockDim.x + threadIdx.x;
  if (i >= n4) return;
  float4 v = in[i];
  __nv_bfloat162 h0 = __float22bfloat162_rn(make_float2(v.x, v.y));
  __nv_bfloat162 h1 = __float22bfloat162_rn(make_float2(v.z, v.w));
  __nv_bfloat162 l0 = __float22bfloat162_rn(make_float2(
      v.x - __bfloat162float(h0.x), v.y - __bfloat162float(h0.y)));
  __nv_bfloat162 l1 = __float22bfloat162_rn(make_float2(
      v.z - __bfloat162float(h1.x), v.w - __bfloat162float(h1.y)));
  hi[2 * i] = h0; hi[2 * i + 1] = h1;
  lo[2 * i] = l0; lo[2 * i + 1] = l1;
}

// ---------------------------------------------------------------------------
// Pack K/V (cache fp32 [s<sp] + fresh roped fp32 [s>=sp]) -> bf16 hi/lo
// concat buffers [B, CT, HKV, D].
// ---------------------------------------------------------------------------
__global__ void pack_kv_kernel(const float* __restrict__ ck,
                               const float* __restrict__ cv,
                               const float* __restrict__ kf,
                               const float* __restrict__ vf,
                               const int* __restrict__ spp,
                               __nv_bfloat162* __restrict__ kh,
                               __nv_bfloat162* __restrict__ kl,
                               __nv_bfloat162* __restrict__ vh,
                               __nv_bfloat162* __restrict__ vl) {
  const int sp = *spp;
  int idx = blockIdx.x * blockDim.x + threadIdx.x;  // over B*CT*HKV*(D/4)
  int d4 = idx & 31;
  int kv = (idx >> 5) & 7;
  int s  = (idx >> 8) & (CT_ - 1);
  int b  = idx >> 20;
  if (b >= B_ || s >= sp + T_) return;

  size_t src;
  const float *kp, *vp;
  if (s < sp) {
    src = (((size_t)b * CT_ + s) * HKV + kv) * D_ + d4 * 4;
    kp = ck; vp = cv;
  } else {
    src = (((size_t)b * T_ + (s - sp)) * HKV + kv) * D_ + d4 * 4;
    kp = kf; vp = vf;
  }
  size_t dst2 = ((((size_t)b * CT_ + s) * HKV + kv) * D_) / 2 + d4 * 2;

  float4 kx = *(const float4*)(kp + src);
  float4 vx = *(const float4*)(vp + src);
#pragma unroll
  for (int half = 0; half < 2; half++) {
    float a0 = half ? kx.z : kx.x, a1 = half ? kx.w : kx.y;
    __nv_bfloat162 h = __float22bfloat162_rn(make_float2(a0, a1));
    __nv_bfloat162 l = __float22bfloat162_rn(make_float2(
        a0 - __bfloat162float(h.x), a1 - __bfloat162float(h.y)));
    kh[dst2 + half] = h; kl[dst2 + half] = l;
    float b0 = half ? vx.z : vx.x, b1 = half ? vx.w : vx.y;
    h = __float22bfloat162_rn(make_float2(b0, b1));
    l = __float22bfloat162_rn(make_float2(
        b0 - __bfloat162float(h.x), b1 - __bfloat162float(h.y)));
    vh[dst2 + half] = h; vl[dst2 + half] = l;
  }
}

// ---------------------------------------------------------------------------
// Tensor-core GEMM (verified in R9): C[M,N] = A[M,K]*B[N,K]^T, 3-term split.
// ---------------------------------------------------------------------------
__global__ void __launch_bounds__(256) gemm_mma_kernel(
    const __nv_bfloat16* __restrict__ Ah, const __nv_bfloat16* __restrict__ Al,
    const __nv_bfloat16* __restrict__ Bh, const __nv_bfloat16* __restrict__ Bl,
    float* __restrict__ C, int M, int N, int K) {
  extern __shared__ char sm[];
  const int tid = threadIdx.x, lane = tid & 31, wid = tid >> 5;
  const int bm = blockIdx.y << 7, bn = blockIdx.x << 7;
  const uint32_t sbase = smem_u32(sm);

  const int warp_m = wid >> 2;
  const int warp_n = wid & 3;

  const __nv_bfloat16* srcs[4] = {Ah, Al, Bh, Bl};

  auto issue = [&](int c, int buf) {
    const int k0 = c << 6;
    const int r = tid >> 1;
    const int s0 = (tid & 1) << 2;
#pragma unroll
    for (int m = 0; m < 4; m++) {
      const __nv_bfloat16* g =
          srcs[m] + (size_t)((m < 2 ? bm : bn) + r) * K + k0;
      uint32_t dstb = sbase + buf * 65536 + m * 16384 + r * 128;
      uint32_t rsw = (uint32_t)(r & 7) << 4;
#pragma unroll
      for (int i = 0; i < 4; i++) {
        int seg = s0 + i;
        cp_async16(dstb + ((uint32_t)(seg << 4) ^ rsw), g + seg * 8);
      }
    }
    asm volatile("cp.async.commit_group;" ::: "memory");
  };

  float acc[4][4][4];
#pragma unroll
  for (int i = 0; i < 4; i++)
#pragma unroll
    for (int j = 0; j < 4; j++)
#pragma unroll
      for (int t = 0; t < 4; t++) acc[i][j][t] = 0.f;

  const int l7 = lane & 7, m1b = (lane >> 3) & 1, m2b = lane >> 4;

  const int nch = K >> 6;
  issue(0, 0);
  for (int c = 0; c < nch; c++) {
    const int buf = c & 1;
    if (c + 1 < nch) {
      issue(c + 1, buf ^ 1);
      asm volatile("cp.async.wait_group 1;" ::: "memory");
    } else {
      asm volatile("cp.async.wait_group 0;" ::: "memory");
    }
    __syncthreads();

    const uint32_t bAh = sbase + buf * 65536;
    const uint32_t bAl = bAh + 16384;
    const uint32_t bBh = bAh + 32768;
    const uint32_t bBl = bAh + 49152;

#pragma unroll
    for (int kk = 0; kk < 4; kk++) {
      uint32_t ah[4][4], al[4][4], bh[2][4], bl[2][4];
#pragma unroll
      for (int i = 0; i < 4; i++) {
        int row = warp_m * 64 + i * 16 + l7 + m1b * 8;
        uint32_t bo = (uint32_t)(kk * 32 + m2b * 16) ^ ((uint32_t)(row & 7) << 4);
        uint32_t ro = (uint32_t)row * 128 + bo;
        ldsm4(ah[i], bAh + ro);
        ldsm4(al[i], bAl + ro);
      }
#pragma unroll
      for (int jp = 0; jp < 2; jp++) {
        int row = warp_n * 32 + jp * 16 + l7 + m2b * 8;
        uint32_t bo = (uint32_t)(kk * 32 + m1b * 16) ^ ((uint32_t)(row & 7) << 4);
        uint32_t ro = (uint32_t)row * 128 + bo;
        ldsm4(bh[jp], bBh + ro);
        ldsm4(bl[jp], bBl + ro);
      }
#pragma unroll
      for (int i = 0; i < 4; i++) {
#pragma unroll
        for (int j = 0; j < 4; j++) {
          uint32_t h0 = bh[j >> 1][(j & 1) * 2], h1 = bh[j >> 1][(j & 1) * 2 + 1];
          uint32_t l0 = bl[j >> 1][(j & 1) * 2], l1 = bl[j >> 1][(j & 1) * 2 + 1];
          mma16816(acc[i][j], ah[i], h0, h1);
          mma16816(acc[i][j], ah[i], l0, l1);
          mma16816(acc[i][j], al[i], h0, h1);
        }
      }
    }
    __syncthreads();
  }

  const int rq = lane >> 2, cq = (lane & 3) << 1;
#pragma unroll
  for (int i = 0; i < 4; i++) {
#pragma unroll
    for (int j = 0; j < 4; j++) {
      int row0 = bm + warp_m * 64 + i * 16 + rq;
      int col = bn + warp_n * 32 + j * 8 + cq;
      *(float2*)(C + (size_t)row0 * N + col) =
          make_float2(acc[i][j][0], acc[i][j][1]);
      *(float2*)(C + (size_t)(row0 + 8) * N + col) =
          make_float2(acc[i][j][2], acc[i][j][3]);
    }
  }
}

// ---------------------------------------------------------------------------
// RoPE (fp32 sincosf)
// ---------------------------------------------------------------------------
__global__ void rope_kernel(float* __restrict__ q, float* __restrict__ k,
                            const int* __restrict__ spp) {
  const int sp = *spp;
  const int qpairs = B_ * T_ * HQ * (D_ / 2);
  const int kpairs = B_ * T_ * HKV * (D_ / 2);
  int idx = blockIdx.x * blockDim.x + threadIdx.x;
  float* base;
  int H;
  if (idx < qpairs) {
    base = q; H = HQ;
  } else {
    idx -= qpairs;
    if (idx >= kpairs) return;
    base = k; H = HKV;
  }
  const int i = idx & 63;
  const int h = (idx >> 6) % H;
  const int m = idx / (64 * H);
  const int t = m % T_;

  const float freq = __expf(-(float)i * (9.210340371976184f / 64.f));
  const float ang  = (float)(sp + t) * freq;
  float s, c;
  sincosf(ang, &s, &c);

  size_t off = ((size_t)m * H + h) * D_ + (i << 1);
  float x1 = base[off], x2 = base[off + 1];
  base[off]     = x1 * c - x2 * s;
  base[off + 1] = x1 * s + x2 * c;
}

// ---------------------------------------------------------------------------
// HMMA flash attention. CTA: 128 q-rows (32 t x 4 g) of one (b, kv head),
// 8 warps x 16 rows, 64-key chunks, cp.async double-buffered K/V.
// smem: Q hi/lo 64KB + 2 x (K hi/lo 32KB + V hi/lo 32KB) = 192KB.
// Panels of 64 d (128B rows), XOR-16B swizzle; QK via 3-term split;
// P hi/lo repack -> PV via ldmatrix.trans, 3-term split.
// ---------------------------------------------------------------------------
__global__ void __launch_bounds__(256) attn_mma_kernel(
    const __nv_bfloat16* __restrict__ qh_, const __nv_bfloat16* __restrict__ ql_,
    const __nv_bfloat16* __restrict__ kh_, const __nv_bfloat16* __restrict__ kl_,
    const __nv_bfloat16* __restrict__ vh_, const __nv_bfloat16* __restrict__ vl_,
    const int* __restrict__ spp, float* __restrict__ ctx) {
  extern __shared__ __align__(1024) char sm[];
  const int sp = *spp;
  const int Stot = sp + T_;
  const int tid = threadIdx.x, lane = tid & 31, w = tid >> 5;
  const int t0 = blockIdx.x << 5;
  const int kv = blockIdx.y;
  const int b  = blockIdx.z;
  const uint32_t sb = smem_u32(sm);
  const uint32_t Qh = sb, Ql = sb + 32768;
  const uint32_t KV0 = sb + 65536;

  // Load Q tile (128 rows x 128 d, hi+lo), rows = t_local*4 + g
#pragma unroll
  for (int it = 0; it < 16; it++) {
    int idx = it * 256 + tid;
    int mat = idx >> 11, rem = idx & 2047;
    int row = rem >> 4, seg = rem & 15;
    int t = t0 + (row >> 2), h = (kv << 2) + (row & 3);
    const __nv_bfloat16* src = (mat ? ql_ : qh_) +
        (((size_t)b * T_ + t) * HQ + h) * D_ + seg * 8;
    uint32_t dst = sb + mat * 32768 + (seg >> 3) * 16384 + (uint32_t)row * 128 +
        (((uint32_t)(seg & 7) << 4) ^ ((uint32_t)(row & 7) << 4));
    cp_async16(dst, src);
  }
  asm volatile("cp.async.commit_group;" ::: "memory");

  const __nv_bfloat16* kvsrc[4] = {kh_, kl_, vh_, vl_};
  auto issue_kv = [&](int c, int buf) {
    const uint32_t base = KV0 + (uint32_t)buf * 65536;
#pragma unroll
    for (int it = 0; it < 16; it++) {
      int idx = it * 256 + tid;
      int mat = idx >> 10, rem = idx & 1023;
      int row = rem >> 4, seg = rem & 15;
      int s = c * 64 + row;
      if (s > Stot - 1) s = Stot - 1;
      const __nv_bfloat16* g = kvsrc[mat] +
          (((size_t)b * CT_ + s) * HKV + kv) * D_ + seg * 8;
      uint32_t dst = base + mat * 16384 + (seg >> 3) * 8192 + (uint32_t)row * 128 +
          (((uint32_t)(seg & 7) << 4) ^ ((uint32_t)(row & 7) << 4));
      cp_async16(dst, g);
    }
    asm volatile("cp.async.commit_group;" ::: "memory");
  };

  float ctxf[16][4];
#pragma unroll
  for (int i = 0; i < 16; i++)
#pragma unroll
    for (int j = 0; j < 4; j++) ctxf[i][j] = 0.f;
  float m0 = -1e30f, m1 = -1e30f, l0 = 0.f, l1 = 0.f;

  const int wbase = w * 16;
  const int l7 = lane & 7, m1b = (lane >> 3) & 1, m2b = lane >> 4;
  const int r0 = wbase + (lane >> 2);
  const int lim0 = sp + t0 + (r0 >> 2);
  const int lim1 = sp + t0 + ((r0 + 8) >> 2);
  const float scale = 0.08838834764831845f;

  const int nch = (sp + t0 + 31) / 64 + 1;
  issue_kv(0, 0);
  for (int c = 0; c < nch; c++) {
    const int buf = c & 1;
    if (c + 1 < nch) {
      issue_kv(c + 1, buf ^ 1);
      asm volatile("cp.async.wait_group 1;" ::: "memory");
    } else {
      asm volatile("cp.async.wait_group 0;" ::: "memory");
    }
    __syncthreads();

    const uint32_t Kh = KV0 + (uint32_t)buf * 65536, Kl = Kh + 16384;
    const uint32_t Vh = Kh + 32768, Vl = Kh + 49152;

    // ---- QK^T (3-term) ----
    float sc[8][4];
#pragma unroll
    for (int j = 0; j < 8; j++)
#pragma unroll
      for (int e = 0; e < 4; e++) sc[j][e] = 0.f;

#pragma unroll
    for (int kk = 0; kk < 8; kk++) {
      int arow = wbase + l7 + m1b * 8;
      uint32_t abo = ((uint32_t)((kk & 3) * 32 + m2b * 16)) ^
                     ((uint32_t)(arow & 7) << 4);
      uint32_t aoff = (uint32_t)(kk >> 2) * 16384 + (uint32_t)arow * 128 + abo;
      uint32_t ah[4], al[4];
      ldsm4(ah, Qh + aoff);
      ldsm4(al, Ql + aoff);
#pragma unroll
      for (int jp = 0; jp < 4; jp++) {
        int brow = jp * 16 + l7 + m2b * 8;
        uint32_t bbo = ((uint32_t)((kk & 3) * 32 + m1b * 16)) ^
                       ((uint32_t)(brow & 7) << 4);
        uint32_t boff = (uint32_t)(kk >> 2) * 8192 + (uint32_t)brow * 128 + bbo;
        uint32_t bh[4], bl[4];
        ldsm4(bh, Kh + boff);
        ldsm4(bl, Kl + boff);
        mma16816(sc[jp * 2], ah, bh[0], bh[1]);
        mma16816(sc[jp * 2], ah, bl[0], bl[1]);
        mma16816(sc[jp * 2], al, bh[0], bh[1]);
        mma16816(sc[jp * 2 + 1], ah, bh[2], bh[3]);
        mma16816(sc[jp * 2 + 1], ah, bl[2], bl[3]);
        mma16816(sc[jp * 2 + 1], al, bh[2], bh[3]);
      }
    }

    // ---- mask + online softmax ----
    const int kbase = c * 64;
    float cm0 = -1e30f, cm1 = -1e30f;
#pragma unroll
    for (int j = 0; j < 8; j++) {
#pragma unroll
      for (int e = 0; e < 2; e++) {
        int key = kbase + j * 8 + 2 * (lane & 3) + e;
        float v0 = sc[j][e] * scale;
        float v1 = sc[j][2 + e] * scale;
        if (key > lim0) v0 = -1e30f;
        if (key > lim1) v1 = -1e30f;
        sc[j][e] = v0; sc[j][2 + e] = v1;
        cm0 = fmaxf(cm0, v0); cm1 = fmaxf(cm1, v1);
      }
    }
    cm0 = fmaxf(cm0, __shfl_xor_sync(0xffffffffu, cm0, 1));
    cm0 = fmaxf(cm0, __shfl_xor_sync(0xffffffffu, cm0, 2));
    cm1 = fmaxf(cm1, __shfl_xor_sync(0xffffffffu, cm1, 1));
    cm1 = fmaxf(cm1, __shfl_xor_sync(0xffffffffu, cm1, 2));
    float mn0 = fmaxf(m0, cm0), mn1 = fmaxf(m1, cm1);
    float s0f = __expf(m0 - mn0), s1f = __expf(m1 - mn1);
    m0 = mn0; m1 = mn1;

    float ps0 = 0.f, ps1 = 0.f;
    uint32_t pkh[8][2], pkl[8][2];
#pragma unroll
    for (int j = 0; j < 8; j++) {
      float p0 = __expf(sc[j][0] - m0), p1 = __expf(sc[j][1] - m0);
      float p2 = __expf(sc[j][2] - m1), p3 = __expf(sc[j][3] - m1);
      ps0 += p0 + p1; ps1 += p2 + p3;
      __nv_bfloat162 h = __float22bfloat162_rn(make_float2(p0, p1));
      __nv_bfloat162 l = __float22bfloat162_rn(make_float2(
          p0 - __bfloat162float(h.x), p1 - __bfloat162float(h.y)));
      pkh[j][0] = *(uint32_t*)&h; pkl[j][0] = *(uint32_t*)&l;
      h = __float22bfloat162_rn(make_float2(p2, p3));
      l = __float22bfloat162_rn(make_float2(
          p2 - __bfloat162float(h.x), p3 - __bfloat162float(h.y)));
      pkh[j][1] = *(uint32_t*)&h; pkl[j][1] = *(uint32_t*)&l;
    }
    ps0 += __shfl_xor_sync(0xffffffffu, ps0, 1);
    ps0 += __shfl_xor_sync(0xffffffffu, ps0, 2);
    ps1 += __shfl_xor_sync(0xffffffffu, ps1, 1);
    ps1 += __shfl_xor_sync(0xffffffffu, ps1, 2);
    l0 = l0 * s0f + ps0;
    l1 = l1 * s1f + ps1;
#pragma unroll
    for (int nt = 0; nt < 16; nt++) {
      ctxf[nt][0] *= s0f; ctxf[nt][1] *= s0f;
      ctxf[nt][2] *= s1f; ctxf[nt][3] *= s1f;
    }

    // ---- P·V (3-term) ----
#pragma unroll
    for (int k0 = 0; k0 < 4; k0++) {
      uint32_t aH[4] = {pkh[2 * k0][0], pkh[2 * k0][1],
                        pkh[2 * k0 + 1][0], pkh[2 * k0 + 1][1]};
      uint32_t aL[4] = {pkl[2 * k0][0], pkl[2 * k0][1],
                        pkl[2 * k0 + 1][0], pkl[2 * k0 + 1][1]};
      const int mI = lane >> 3, iI = lane & 7;
      const int keyr = k0 * 16 + iI + (mI & 1) * 8;
#pragma unroll
      for (int nn = 0; nn < 8; nn++) {
        int dstart = nn * 16 + (mI >> 1) * 8;
        uint32_t voff = (uint32_t)(dstart >> 6) * 8192 + (uint32_t)keyr * 128 +
            (((uint32_t)(dstart & 63) * 2) ^ ((uint32_t)(keyr & 7) << 4));
        uint32_t bh[4], bl[4];
        ldsm4t(bh, Vh + voff);
        ldsm4t(bl, Vl + voff);
        mma16816(ctxf[2 * nn], aH, bh[0], bh[1]);
        mma16816(ctxf[2 * nn], aH, bl[0], bl[1]);
        mma16816(ctxf[2 * nn], aL, bh[0], bh[1]);
        mma16816(ctxf[2 * nn + 1], aH, bh[2], bh[3]);
        mma16816(ctxf[2 * nn + 1], aH, bl[2], bl[3]);
        mma16816(ctxf[2 * nn + 1], aL, bh[2], bh[3]);
      }
    }
    __syncthreads();
  }

  // ---- epilogue ----
  const float il0 = 1.f / l0, il1 = 1.f / l1;
  const int tq0 = t0 + (r0 >> 2), tq1 = t0 + ((r0 + 8) >> 2);
  const int h = (kv << 2) + (r0 & 3);
  size_t o0 = (((size_t)b * T_ + tq0) * HQ + h) * (size_t)D_;
  size_t o1 = (((size_t)b * T_ + tq1) * HQ + h) * (size_t)D_;
#pragma unroll
  for (int nt = 0; nt < 16; nt++) {
    int d = nt * 8 + 2 * (lane & 3);
    *(float2*)(ctx + o0 + d) = make_float2(ctxf[nt][0] * il0, ctxf[nt][1] * il0);
    *(float2*)(ctx + o1 + d) = make_float2(ctxf[nt][2] * il1, ctxf[nt][3] * il1);
  }
}

// ---------------------------------------------------------------------------
// kernel_launch
// ---------------------------------------------------------------------------
extern "C" void kernel_launch(void* const* d_in, const int* in_sizes, int n_in,
                              void* d_out, int out_size) {
  const float* x  = (const float*)d_in[0];
  const int*   sp = (const int*)  d_in[1];
  const float* ck = (const float*)d_in[2];
  const float* cv = (const float*)d_in[3];
  const float* Wq = (const float*)d_in[4];
  const float* Wk = (const float*)d_in[5];
  const float* Wv = (const float*)d_in[6];
  const float* Wo = (const float*)d_in[7];
  float* out = (float*)d_out;

  constexpr int GEMM_SMEM = 131072;
  constexpr int ATTN_SMEM = 196608;

  static float *qb, *kb, *vb, *cb;
  static __nv_bfloat16 *xh, *xl, *wqh, *wql, *wkh, *wkl, *wvh, *wvl, *woh, *wol,
      *cth, *ctl, *qah, *qal, *kch, *kcl, *vch, *vcl;
  static bool init_done = false;
  if (!init_done) {
    cudaGetSymbolAddress((void**)&qb, g_q);
    cudaGetSymbolAddress((void**)&kb, g_k);
    cudaGetSymbolAddress((void**)&vb, g_v);
    cudaGetSymbolAddress((void**)&cb, g_ctx);
    cudaGetSymbolAddress((void**)&xh, g_xh);
    cudaGetSymbolAddress((void**)&xl, g_xl);
    cudaGetSymbolAddress((void**)&wqh, g_wqh);
    cudaGetSymbolAddress((void**)&wql, g_wql);
    cudaGetSymbolAddress((void**)&wkh, g_wkh);
    cudaGetSymbolAddress((void**)&wkl, g_wkl);
    cudaGetSymbolAddress((void**)&wvh, g_wvh);
    cudaGetSymbolAddress((void**)&wvl, g_wvl);
    cudaGetSymbolAddress((void**)&woh, g_woh);
    cudaGetSymbolAddress((void**)&wol, g_wol);
    cudaGetSymbolAddress((void**)&cth, g_cth);
    cudaGetSymbolAddress((void**)&ctl, g_ctl);
    cudaGetSymbolAddress((void**)&qah, g_qah);
    cudaGetSymbolAddress((void**)&qal, g_qal);
    cudaGetSymbolAddress((void**)&kch, g_kch);
    cudaGetSymbolAddress((void**)&kcl, g_kcl);
    cudaGetSymbolAddress((void**)&vch, g_vch);
    cudaGetSymbolAddress((void**)&vcl, g_vcl);
    cudaFuncSetAttribute(gemm_mma_kernel,
                         cudaFuncAttributeMaxDynamicSharedMemorySize, GEMM_SMEM);
    cudaFuncSetAttribute(attn_mma_kernel,
                         cudaFuncAttributeMaxDynamicSharedMemorySize, ATTN_SMEM);
    init_done = true;
  }

  const int M = B_ * T_;  // 2048

  // fp32 -> bf16 hi/lo conversions (x, weights)
  const int n4x = M * C_ / 4;
  const int n4q = C_ * C_ / 4;
  const int n4k = HKV * D_ * C_ / 4;
  cvt_kernel<<<(n4x + 255) / 256, 256>>>((const float4*)x,
      (__nv_bfloat162*)xh, (__nv_bfloat162*)xl, n4x);
  cvt_kernel<<<(n4q + 255) / 256, 256>>>((const float4*)Wq,
      (__nv_bfloat162*)wqh, (__nv_bfloat162*)wql, n4q);
  cvt_kernel<<<(n4k + 255) / 256, 256>>>((const float4*)Wk,
      (__nv_bfloat162*)wkh, (__nv_bfloat162*)wkl, n4k);
  cvt_kernel<<<(n4k + 255) / 256, 256>>>((const float4*)Wv,
      (__nv_bfloat162*)wvh, (__nv_bfloat162*)wvl, n4k);
  cvt_kernel<<<(n4q + 255) / 256, 256>>>((const float4*)Wo,
      (__nv_bfloat162*)woh, (__nv_bfloat162*)wol, n4q);

  // QKV projections (tensor cores)
  gemm_mma_kernel<<<dim3(C_ / 128, M / 128), 256, GEMM_SMEM>>>(
      xh, xl, wqh, wql, qb, M, C_, C_);
  gemm_mma_kernel<<<dim3((HKV * D_) / 128, M / 128), 256, GEMM_SMEM>>>(
      xh, xl, wkh, wkl, kb, M, HKV * D_, C_);
  gemm_mma_kernel<<<dim3((HKV * D_) / 128, M / 128), 256, GEMM_SMEM>>>(
      xh, xl, wvh, wvl, vb, M, HKV * D_, C_);

  // RoPE on fresh q, k (fp32 in place)
  const int totalpairs = M * HQ * (D_ / 2) + M * HKV * (D_ / 2);
  rope_kernel<<<(totalpairs + 255) / 256, 256>>>(qb, kb, sp);

  // Pack attention operands to bf16 hi/lo
  cvt_kernel<<<(M * HQ * D_ / 4 + 255) / 256, 256>>>((const float4*)qb,
      (__nv_bfloat162*)qah, (__nv_bfloat162*)qal, M * HQ * D_ / 4);
  const int npack = B_ * CT_ * HKV * (D_ / 4);
  pack_kv_kernel<<<(npack + 255) / 256, 256>>>(ck, cv, kb, vb, sp,
      (__nv_bfloat162*)kch, (__nv_bfloat162*)kcl,
      (__nv_bfloat162*)vch, (__nv_bfloat162*)vcl);

  // HMMA flash attention: grid (T/32, HKV, B)
  attn_mma_kernel<<<dim3(T_ / 32, HKV, B_), 256, ATTN_SMEM>>>(
      qah, qal, kch, kcl, vch, vcl, sp, cb);

  // ctx -> bf16 hi/lo, then output projection
  cvt_kernel<<<(n4x + 255) / 256, 256>>>((const float4*)cb,
      (__nv_bfloat162*)cth, (__nv_bfloat162*)ctl, n4x);
  gemm_mma_kernel<<<dim3(C_ / 128, M / 128), 256, GEMM_SMEM>>>(
      cth, ctl, woh, wol, out, M, C_, C_);
}

// round 11
// speedup vs baseline: 3.4048x; 1.0048x over previous
#include <cuda_runtime.h>
#include <cuda_bf16.h>
#include <cuda_fp16.h>
#include <cstdint>
#include <math.h>

// Problem constants
constexpr int B_   = 2;
constexpr int T_   = 1024;
constexpr int C_   = 4096;
constexpr int HQ   = 32;
constexpr int HKV  = 8;
constexpr int D_   = 128;
constexpr int G_   = 4;
constexpr int CT_  = 4096;

// fp32 scratch
__device__ float g_q  [(size_t)B_ * T_ * HQ  * D_];
__device__ float g_k  [(size_t)B_ * T_ * HKV * D_];
__device__ float g_v  [(size_t)B_ * T_ * HKV * D_];

// bf16 hi/lo scratch for tensor-core GEMMs
__device__ __nv_bfloat16 g_xh [(size_t)B_ * T_ * C_];
__device__ __nv_bfloat16 g_xl [(size_t)B_ * T_ * C_];
__device__ __nv_bfloat16 g_wqh[(size_t)C_ * C_];
__device__ __nv_bfloat16 g_wql[(size_t)C_ * C_];
__device__ __nv_bfloat16 g_wkh[(size_t)HKV * D_ * C_];
__device__ __nv_bfloat16 g_wkl[(size_t)HKV * D_ * C_];
__device__ __nv_bfloat16 g_wvh[(size_t)HKV * D_ * C_];
__device__ __nv_bfloat16 g_wvl[(size_t)HKV * D_ * C_];
__device__ __nv_bfloat16 g_woh[(size_t)C_ * C_];
__device__ __nv_bfloat16 g_wol[(size_t)C_ * C_];
__device__ __nv_bfloat16 g_cth[(size_t)B_ * T_ * C_];
__device__ __nv_bfloat16 g_ctl[(size_t)B_ * T_ * C_];

// bf16 hi/lo attention operands
__device__ __nv_bfloat16 g_qah[(size_t)B_ * T_ * HQ * D_];
__device__ __nv_bfloat16 g_qal[(size_t)B_ * T_ * HQ * D_];
__device__ __nv_bfloat16 g_kch[(size_t)B_ * CT_ * HKV * D_];
__device__ __nv_bfloat16 g_kcl[(size_t)B_ * CT_ * HKV * D_];
__device__ __nv_bfloat16 g_vch[(size_t)B_ * CT_ * HKV * D_];
__device__ __nv_bfloat16 g_vcl[(size_t)B_ * CT_ * HKV * D_];

__device__ __forceinline__ uint32_t smem_u32(const void* p) {
  uint32_t a;
  asm("{ .reg .u64 t; cvta.to.shared.u64 t, %1; cvt.u32.u64 %0, t; }"
      : "=r"(a) : "l"(p));
  return a;
}

__device__ __forceinline__ void ldsm4(uint32_t* r, uint32_t addr) {
  asm volatile("ldmatrix.sync.aligned.m8n8.x4.shared.b16 {%0,%1,%2,%3}, [%4];"
               : "=r"(r[0]), "=r"(r[1]), "=r"(r[2]), "=r"(r[3]) : "r"(addr));
}

__device__ __forceinline__ void ldsm4t(uint32_t* r, uint32_t addr) {
  asm volatile("ldmatrix.sync.aligned.m8n8.x4.trans.shared.b16 {%0,%1,%2,%3}, [%4];"
               : "=r"(r[0]), "=r"(r[1]), "=r"(r[2]), "=r"(r[3]) : "r"(addr));
}

__device__ __forceinline__ void mma16816(float* d, const uint32_t* a,
                                         uint32_t b0, uint32_t b1) {
  asm volatile(
      "mma.sync.aligned.m16n8k16.row.col.f32.bf16.bf16.f32 "
      "{%0,%1,%2,%3},{%4,%5,%6,%7},{%8,%9},{%0,%1,%2,%3};"
      : "+f"(d[0]), "+f"(d[1]), "+f"(d[2]), "+f"(d[3])
      : "r"(a[0]), "r"(a[1]), "r"(a[2]), "r"(a[3]), "r"(b0), "r"(b1));
}

__device__ __forceinline__ void cp_async16(uint32_t dst, const void* src) {
  asm volatile("cp.async.cg.shared.global [%0], [%1], 16;"
               :: "r"(dst), "l"(src) : "memory");
}

__device__ __forceinline__ void split2(float a0, float a1, __nv_bfloat162& h,
                                       __nv_bfloat162& l) {
  h = __float22bfloat162_rn(make_float2(a0, a1));
  l = __float22bfloat162_rn(make_float2(a0 - __bfloat162float(h.x),
                                        a1 - __bfloat162float(h.y)));
}

// ---------------------------------------------------------------------------
// fp32 -> bf16 hi/lo split (elementwise)
// ---------------------------------------------------------------------------
__global__ void cvt_kernel(const float4* __restrict__ in,
                           __nv_bfloat162* __restrict__ hi,
                           __nv_bfloat162* __restrict__ lo, int n4) {
  int i = blockIdx.x * blockDim.x + threadIdx.x;
  if (i >= n4) return;
  float4 v = in[i];
  __nv_bfloat162 h0, l0, h1, l1;
  split2(v.x, v.y, h0, l0);
  split2(v.z, v.w, h1, l1);
  hi[2 * i] = h0; hi[2 * i + 1] = h1;
  lo[2 * i] = l0; lo[2 * i + 1] = l1;
}

// ---------------------------------------------------------------------------
// Fused rope + split + pack for fresh q/k/v.
// q: rope -> qah/qal.  k: rope -> kch/kcl at s=sp+t.  v: split -> vch/vcl.
// ---------------------------------------------------------------------------
__global__ void rope_pack_kernel(const float* __restrict__ q,
                                 const float* __restrict__ k,
                                 const float* __restrict__ v,
                                 const int* __restrict__ spp,
                                 __nv_bfloat162* __restrict__ qh,
                                 __nv_bfloat162* __restrict__ ql,
                                 __nv_bfloat162* __restrict__ kh,
                                 __nv_bfloat162* __restrict__ kl,
                                 __nv_bfloat162* __restrict__ vh,
                                 __nv_bfloat162* __restrict__ vl) {
  const int sp = *spp;
  const int M = B_ * T_;
  const int qpairs = M * HQ * 64;
  const int kpairs = M * HKV * 64;
  int idx = blockIdx.x * blockDim.x + threadIdx.x;

  if (idx < qpairs) {
    const int i = idx & 63, h = (idx >> 6) & 31, m = idx >> 11;
    const int t = m % T_;
    const float freq = __expf(-(float)i * (9.210340371976184f / 64.f));
    float s, c;
    sincosf((float)(sp + t) * freq, &s, &c);
    float2 x = *(const float2*)(q + 2 * (size_t)idx);
    float o0 = x.x * c - x.y * s, o1 = x.x * s + x.y * c;
    __nv_bfloat162 hh, ll;
    split2(o0, o1, hh, ll);
    qh[idx] = hh; ql[idx] = ll;
    return;
  }
  idx -= qpairs;
  if (idx < kpairs) {
    const int i = idx & 63, kv = (idx >> 6) & 7, m = idx >> 9;
    const int t = m % T_, b = m / T_;
    const float freq = __expf(-(float)i * (9.210340371976184f / 64.f));
    float s, c;
    sincosf((float)(sp + t) * freq, &s, &c);
    float2 x = *(const float2*)(k + 2 * (size_t)idx);
    float o0 = x.x * c - x.y * s, o1 = x.x * s + x.y * c;
    __nv_bfloat162 hh, ll;
    split2(o0, o1, hh, ll);
    size_t dst = (((size_t)b * CT_ + sp + t) * HKV + kv) * 64 + i;
    kh[dst] = hh; kl[dst] = ll;
    return;
  }
  idx -= kpairs;
  if (idx >= kpairs) return;
  const int i = idx & 63, kv = (idx >> 6) & 7, m = idx >> 9;
  const int t = m % T_, b = m / T_;
  float2 x = *(const float2*)(v + 2 * (size_t)idx);
  __nv_bfloat162 hh, ll;
  split2(x.x, x.y, hh, ll);
  size_t dst = (((size_t)b * CT_ + sp + t) * HKV + kv) * 64 + i;
  vh[dst] = hh; vl[dst] = ll;
}

// ---------------------------------------------------------------------------
// Pack cache K/V (s < sp only) -> bf16 hi/lo concat buffers.
// ---------------------------------------------------------------------------
__global__ void pack_cache_kernel(const float* __restrict__ ck,
                                  const float* __restrict__ cv,
                                  const int* __restrict__ spp,
                                  __nv_bfloat162* __restrict__ kh,
                                  __nv_bfloat162* __restrict__ kl,
                                  __nv_bfloat162* __restrict__ vh,
                                  __nv_bfloat162* __restrict__ vl) {
  const int sp = *spp;
  int idx = blockIdx.x * blockDim.x + threadIdx.x;  // over B*CT*HKV*(D/4)
  int d4 = idx & 31;
  int kv = (idx >> 5) & 7;
  int s  = (idx >> 8) & (CT_ - 1);
  int b  = idx >> 20;
  if (b >= B_ || s >= sp) return;

  size_t src = (((size_t)b * CT_ + s) * HKV + kv) * D_ + d4 * 4;
  size_t dst2 = ((((size_t)b * CT_ + s) * HKV + kv) * D_) / 2 + d4 * 2;

  float4 kx = *(const float4*)(ck + src);
  float4 vx = *(const float4*)(cv + src);
  __nv_bfloat162 h, l;
  split2(kx.x, kx.y, h, l); kh[dst2] = h; kl[dst2] = l;
  split2(kx.z, kx.w, h, l); kh[dst2 + 1] = h; kl[dst2 + 1] = l;
  split2(vx.x, vx.y, h, l); vh[dst2] = h; vl[dst2] = l;
  split2(vx.z, vx.w, h, l); vh[dst2 + 1] = h; vl[dst2 + 1] = l;
}

// ---------------------------------------------------------------------------
// Tensor-core GEMM (verified): C[M,N] = A[M,K]*B[N,K]^T, 3-term split.
// ---------------------------------------------------------------------------
__global__ void __launch_bounds__(256) gemm_mma_kernel(
    const __nv_bfloat16* __restrict__ Ah, const __nv_bfloat16* __restrict__ Al,
    const __nv_bfloat16* __restrict__ Bh, const __nv_bfloat16* __restrict__ Bl,
    float* __restrict__ C, int M, int N, int K) {
  extern __shared__ char sm[];
  const int tid = threadIdx.x, lane = tid & 31, wid = tid >> 5;
  const int bm = blockIdx.y << 7, bn = blockIdx.x << 7;
  const uint32_t sbase = smem_u32(sm);

  const int warp_m = wid >> 2;
  const int warp_n = wid & 3;

  const __nv_bfloat16* srcs[4] = {Ah, Al, Bh, Bl};

  auto issue = [&](int c, int buf) {
    const int k0 = c << 6;
    const int r = tid >> 1;
    const int s0 = (tid & 1) << 2;
#pragma unroll
    for (int m = 0; m < 4; m++) {
      const __nv_bfloat16* g =
          srcs[m] + (size_t)((m < 2 ? bm : bn) + r) * K + k0;
      uint32_t dstb = sbase + buf * 65536 + m * 16384 + r * 128;
      uint32_t rsw = (uint32_t)(r & 7) << 4;
#pragma unroll
      for (int i = 0; i < 4; i++) {
        int seg = s0 + i;
        cp_async16(dstb + ((uint32_t)(seg << 4) ^ rsw), g + seg * 8);
      }
    }
    asm volatile("cp.async.commit_group;" ::: "memory");
  };

  float acc[4][4][4];
#pragma unroll
  for (int i = 0; i < 4; i++)
#pragma unroll
    for (int j = 0; j < 4; j++)
#pragma unroll
      for (int t = 0; t < 4; t++) acc[i][j][t] = 0.f;

  const int l7 = lane & 7, m1b = (lane >> 3) & 1, m2b = lane >> 4;

  const int nch = K >> 6;
  issue(0, 0);
  for (int c = 0; c < nch; c++) {
    const int buf = c & 1;
    if (c + 1 < nch) {
      issue(c + 1, buf ^ 1);
      asm volatile("cp.async.wait_group 1;" ::: "memory");
    } else {
      asm volatile("cp.async.wait_group 0;" ::: "memory");
    }
    __syncthreads();

    const uint32_t bAh = sbase + buf * 65536;
    const uint32_t bAl = bAh + 16384;
    const uint32_t bBh = bAh + 32768;
    const uint32_t bBl = bAh + 49152;

#pragma unroll
    for (int kk = 0; kk < 4; kk++) {
      uint32_t ah[4][4], al[4][4], bh[2][4], bl[2][4];
#pragma unroll
      for (int i = 0; i < 4; i++) {
        int row = warp_m * 64 + i * 16 + l7 + m1b * 8;
        uint32_t bo = (uint32_t)(kk * 32 + m2b * 16) ^ ((uint32_t)(row & 7) << 4);
        uint32_t ro = (uint32_t)row * 128 + bo;
        ldsm4(ah[i], bAh + ro);
        ldsm4(al[i], bAl + ro);
      }
#pragma unroll
      for (int jp = 0; jp < 2; jp++) {
        int row = warp_n * 32 + jp * 16 + l7 + m2b * 8;
        uint32_t bo = (uint32_t)(kk * 32 + m1b * 16) ^ ((uint32_t)(row & 7) << 4);
        uint32_t ro = (uint32_t)row * 128 + bo;
        ldsm4(bh[jp], bBh + ro);
        ldsm4(bl[jp], bBl + ro);
      }
#pragma unroll
      for (int i = 0; i < 4; i++) {
#pragma unroll
        for (int j = 0; j < 4; j++) {
          uint32_t h0 = bh[j >> 1][(j & 1) * 2], h1 = bh[j >> 1][(j & 1) * 2 + 1];
          uint32_t l0 = bl[j >> 1][(j & 1) * 2], l1 = bl[j >> 1][(j & 1) * 2 + 1];
          mma16816(acc[i][j], ah[i], h0, h1);
          mma16816(acc[i][j], ah[i], l0, l1);
          mma16816(acc[i][j], al[i], h0, h1);
        }
      }
    }
    __syncthreads();
  }

  const int rq = lane >> 2, cq = (lane & 3) << 1;
#pragma unroll
  for (int i = 0; i < 4; i++) {
#pragma unroll
    for (int j = 0; j < 4; j++) {
      int row0 = bm + warp_m * 64 + i * 16 + rq;
      int col = bn + warp_n * 32 + j * 8 + cq;
      *(float2*)(C + (size_t)row0 * N + col) =
          make_float2(acc[i][j][0], acc[i][j][1]);
      *(float2*)(C + (size_t)(row0 + 8) * N + col) =
          make_float2(acc[i][j][2], acc[i][j][3]);
    }
  }
}

// ---------------------------------------------------------------------------
// HMMA flash attention (verified R10 structure) + f16x2 exp softmax +
// direct bf16 hi/lo context output.
// ---------------------------------------------------------------------------
__global__ void __launch_bounds__(256) attn_mma_kernel(
    const __nv_bfloat16* __restrict__ qh_, const __nv_bfloat16* __restrict__ ql_,
    const __nv_bfloat16* __restrict__ kh_, const __nv_bfloat16* __restrict__ kl_,
    const __nv_bfloat16* __restrict__ vh_, const __nv_bfloat16* __restrict__ vl_,
    const int* __restrict__ spp, __nv_bfloat162* __restrict__ cth,
    __nv_bfloat162* __restrict__ ctl) {
  extern __shared__ __align__(1024) char sm[];
  const int sp = *spp;
  const int Stot = sp + T_;
  const int tid = threadIdx.x, lane = tid & 31, w = tid >> 5;
  const int t0 = blockIdx.x << 5;
  const int kv = blockIdx.y;
  const int b  = blockIdx.z;
  const uint32_t sb = smem_u32(sm);
  const uint32_t Qh = sb, Ql = sb + 32768;
  const uint32_t KV0 = sb + 65536;

#pragma unroll
  for (int it = 0; it < 16; it++) {
    int idx = it * 256 + tid;
    int mat = idx >> 11, rem = idx & 2047;
    int row = rem >> 4, seg = rem & 15;
    int t = t0 + (row >> 2), h = (kv << 2) + (row & 3);
    const __nv_bfloat16* src = (mat ? ql_ : qh_) +
        (((size_t)b * T_ + t) * HQ + h) * D_ + seg * 8;
    uint32_t dst = sb + mat * 32768 + (seg >> 3) * 16384 + (uint32_t)row * 128 +
        (((uint32_t)(seg & 7) << 4) ^ ((uint32_t)(row & 7) << 4));
    cp_async16(dst, src);
  }
  asm volatile("cp.async.commit_group;" ::: "memory");

  const __nv_bfloat16* kvsrc[4] = {kh_, kl_, vh_, vl_};
  auto issue_kv = [&](int c, int buf) {
    const uint32_t base = KV0 + (uint32_t)buf * 65536;
#pragma unroll
    for (int it = 0; it < 16; it++) {
      int idx = it * 256 + tid;
      int mat = idx >> 10, rem = idx & 1023;
      int row = rem >> 4, seg = rem & 15;
      int s = c * 64 + row;
      if (s > Stot - 1) s = Stot - 1;
      const __nv_bfloat16* g = kvsrc[mat] +
          (((size_t)b * CT_ + s) * HKV + kv) * D_ + seg * 8;
      uint32_t dst = base + mat * 16384 + (seg >> 3) * 8192 + (uint32_t)row * 128 +
          (((uint32_t)(seg & 7) << 4) ^ ((uint32_t)(row & 7) << 4));
      cp_async16(dst, g);
    }
    asm volatile("cp.async.commit_group;" ::: "memory");
  };

  float ctxf[16][4];
#pragma unroll
  for (int i = 0; i < 16; i++)
#pragma unroll
    for (int j = 0; j < 4; j++) ctxf[i][j] = 0.f;
  float m0 = -1e30f, m1 = -1e30f, l0 = 0.f, l1 = 0.f;

  const int wbase = w * 16;
  const int l7 = lane & 7, m1b = (lane >> 3) & 1, m2b = lane >> 4;
  const int r0 = wbase + (lane >> 2);
  const int lim0 = sp + t0 + (r0 >> 2);
  const int lim1 = sp + t0 + ((r0 + 8) >> 2);
  const float scale = 0.08838834764831845f;
  const float L2E = 1.4426950408889634f;

  const int nch = (sp + t0 + 31) / 64 + 1;
  issue_kv(0, 0);
  for (int c = 0; c < nch; c++) {
    const int buf = c & 1;
    if (c + 1 < nch) {
      issue_kv(c + 1, buf ^ 1);
      asm volatile("cp.async.wait_group 1;" ::: "memory");
    } else {
      asm volatile("cp.async.wait_group 0;" ::: "memory");
    }
    __syncthreads();

    const uint32_t Kh = KV0 + (uint32_t)buf * 65536, Kl = Kh + 16384;
    const uint32_t Vh = Kh + 32768, Vl = Kh + 49152;

    // ---- QK^T (3-term) ----
    float sc[8][4];
#pragma unroll
    for (int j = 0; j < 8; j++)
#pragma unroll
      for (int e = 0; e < 4; e++) sc[j][e] = 0.f;

#pragma unroll
    for (int kk = 0; kk < 8; kk++) {
      int arow = wbase + l7 + m1b * 8;
      uint32_t abo = ((uint32_t)((kk & 3) * 32 + m2b * 16)) ^
                     ((uint32_t)(arow & 7) << 4);
      uint32_t aoff = (uint32_t)(kk >> 2) * 16384 + (uint32_t)arow * 128 + abo;
      uint32_t ah[4], al[4];
      ldsm4(ah, Qh + aoff);
      ldsm4(al, Ql + aoff);
#pragma unroll
      for (int jp = 0; jp < 4; jp++) {
        int brow = jp * 16 + l7 + m2b * 8;
        uint32_t bbo = ((uint32_t)((kk & 3) * 32 + m1b * 16)) ^
                       ((uint32_t)(brow & 7) << 4);
        uint32_t boff = (uint32_t)(kk >> 2) * 8192 + (uint32_t)brow * 128 + bbo;
        uint32_t bh[4], bl[4];
        ldsm4(bh, Kh + boff);
        ldsm4(bl, Kl + boff);
        mma16816(sc[jp * 2], ah, bh[0], bh[1]);
        mma16816(sc[jp * 2], ah, bl[0], bl[1]);
        mma16816(sc[jp * 2], al, bh[0], bh[1]);
        mma16816(sc[jp * 2 + 1], ah, bh[2], bh[3]);
        mma16816(sc[jp * 2 + 1], ah, bl[2], bl[3]);
        mma16816(sc[jp * 2 + 1], al, bh[2], bh[3]);
      }
    }

    // ---- mask + online softmax ----
    const int kbase = c * 64;
    float cm0 = -1e30f, cm1 = -1e30f;
#pragma unroll
    for (int j = 0; j < 8; j++) {
#pragma unroll
      for (int e = 0; e < 2; e++) {
        int key = kbase + j * 8 + 2 * (lane & 3) + e;
        float v0 = sc[j][e] * scale;
        float v1 = sc[j][2 + e] * scale;
        if (key > lim0) v0 = -1e30f;
        if (key > lim1) v1 = -1e30f;
        sc[j][e] = v0; sc[j][2 + e] = v1;
        cm0 = fmaxf(cm0, v0); cm1 = fmaxf(cm1, v1);
      }
    }
    cm0 = fmaxf(cm0, __shfl_xor_sync(0xffffffffu, cm0, 1));
    cm0 = fmaxf(cm0, __shfl_xor_sync(0xffffffffu, cm0, 2));
    cm1 = fmaxf(cm1, __shfl_xor_sync(0xffffffffu, cm1, 1));
    cm1 = fmaxf(cm1, __shfl_xor_sync(0xffffffffu, cm1, 2));
    float mn0 = fmaxf(m0, cm0), mn1 = fmaxf(m1, cm1);
    float s0f = __expf(m0 - mn0), s1f = __expf(m1 - mn1);
    m0 = mn0; m1 = mn1;
    const float m0L = m0 * L2E, m1L = m1 * L2E;

    float ps0 = 0.f, ps1 = 0.f;
    uint32_t pkh[8][2], pkl[8][2];
#pragma unroll
    for (int j = 0; j < 8; j++) {
      // f16x2 exp2: one MUFU per two probs
      float y0 = fmaf(sc[j][0], L2E, -m0L), y1 = fmaf(sc[j][1], L2E, -m0L);
      float y2 = fmaf(sc[j][2], L2E, -m1L), y3 = fmaf(sc[j][3], L2E, -m1L);
      float2 p01 = __half22float2(h2exp2(__floats2half2_rn(y0, y1)));
      float2 p23 = __half22float2(h2exp2(__floats2half2_rn(y2, y3)));
      float p0 = p01.x, p1 = p01.y, p2 = p23.x, p3 = p23.y;
      ps0 += p0 + p1; ps1 += p2 + p3;
      __nv_bfloat162 h, l;
      split2(p0, p1, h, l);
      pkh[j][0] = *(uint32_t*)&h; pkl[j][0] = *(uint32_t*)&l;
      split2(p2, p3, h, l);
      pkh[j][1] = *(uint32_t*)&h; pkl[j][1] = *(uint32_t*)&l;
    }
    ps0 += __shfl_xor_sync(0xffffffffu, ps0, 1);
    ps0 += __shfl_xor_sync(0xffffffffu, ps0, 2);
    ps1 += __shfl_xor_sync(0xffffffffu, ps1, 1);
    ps1 += __shfl_xor_sync(0xffffffffu, ps1, 2);
    l0 = l0 * s0f + ps0;
    l1 = l1 * s1f + ps1;
#pragma unroll
    for (int nt = 0; nt < 16; nt++) {
      ctxf[nt][0] *= s0f; ctxf[nt][1] *= s0f;
      ctxf[nt][2] *= s1f; ctxf[nt][3] *= s1f;
    }

    // ---- P·V (3-term) ----
#pragma unroll
    for (int k0 = 0; k0 < 4; k0++) {
      uint32_t aH[4] = {pkh[2 * k0][0], pkh[2 * k0][1],
                        pkh[2 * k0 + 1][0], pkh[2 * k0 + 1][1]};
      uint32_t aL[4] = {pkl[2 * k0][0], pkl[2 * k0][1],
                        pkl[2 * k0 + 1][0], pkl[2 * k0 + 1][1]};
      const int mI = lane >> 3, iI = lane & 7;
      const int keyr = k0 * 16 + iI + (mI & 1) * 8;
#pragma unroll
      for (int nn = 0; nn < 8; nn++) {
        int dstart = nn * 16 + (mI >> 1) * 8;
        uint32_t voff = (uint32_t)(dstart >> 6) * 8192 + (uint32_t)keyr * 128 +
            (((uint32_t)(dstart & 63) * 2) ^ ((uint32_t)(keyr & 7) << 4));
        uint32_t bh[4], bl[4];
        ldsm4t(bh, Vh + voff);
        ldsm4t(bl, Vl + voff);
        mma16816(ctxf[2 * nn], aH, bh[0], bh[1]);
        mma16816(ctxf[2 * nn], aH, bl[0], bl[1]);
        mma16816(ctxf[2 * nn], aL, bh[0], bh[1]);
        mma16816(ctxf[2 * nn + 1], aH, bh[2], bh[3]);
        mma16816(ctxf[2 * nn + 1], aH, bl[2], bl[3]);
        mma16816(ctxf[2 * nn + 1], aL, bh[2], bh[3]);
      }
    }
    __syncthreads();
  }

  // ---- epilogue: write bf16 hi/lo ctx directly ----
  const float il0 = 1.f / l0, il1 = 1.f / l1;
  const int tq0 = t0 + (r0 >> 2), tq1 = t0 + ((r0 + 8) >> 2);
  const int h = (kv << 2) + (r0 & 3);
  size_t o0 = (((size_t)b * T_ + tq0) * HQ + h) * (size_t)D_;
  size_t o1 = (((size_t)b * T_ + tq1) * HQ + h) * (size_t)D_;
#pragma unroll
  for (int nt = 0; nt < 16; nt++) {
    int d = nt * 8 + 2 * (lane & 3);
    __nv_bfloat162 hh, ll;
    split2(ctxf[nt][0] * il0, ctxf[nt][1] * il0, hh, ll);
    cth[(o0 + d) >> 1] = hh; ctl[(o0 + d) >> 1] = ll;
    split2(ctxf[nt][2] * il1, ctxf[nt][3] * il1, hh, ll);
    cth[(o1 + d) >> 1] = hh; ctl[(o1 + d) >> 1] = ll;
  }
}

// ---------------------------------------------------------------------------
// kernel_launch
// ---------------------------------------------------------------------------
extern "C" void kernel_launch(void* const* d_in, const int* in_sizes, int n_in,
                              void* d_out, int out_size) {
  const float* x  = (const float*)d_in[0];
  const int*   sp = (const int*)  d_in[1];
  const float* ck = (const float*)d_in[2];
  const float* cv = (const float*)d_in[3];
  const float* Wq = (const float*)d_in[4];
  const float* Wk = (const float*)d_in[5];
  const float* Wv = (const float*)d_in[6];
  const float* Wo = (const float*)d_in[7];
  float* out = (float*)d_out;

  constexpr int GEMM_SMEM = 131072;
  constexpr int ATTN_SMEM = 196608;

  static float *qb, *kb, *vb;
  static __nv_bfloat16 *xh, *xl, *wqh, *wql, *wkh, *wkl, *wvh, *wvl, *woh, *wol,
      *cth, *ctl, *qah, *qal, *kch, *kcl, *vch, *vcl;
  static bool init_done = false;
  if (!init_done) {
    cudaGetSymbolAddress((void**)&qb, g_q);
    cudaGetSymbolAddress((void**)&kb, g_k);
    cudaGetSymbolAddress((void**)&vb, g_v);
    cudaGetSymbolAddress((void**)&xh, g_xh);
    cudaGetSymbolAddress((void**)&xl, g_xl);
    cudaGetSymbolAddress((void**)&wqh, g_wqh);
    cudaGetSymbolAddress((void**)&wql, g_wql);
    cudaGetSymbolAddress((void**)&wkh, g_wkh);
    cudaGetSymbolAddress((void**)&wkl, g_wkl);
    cudaGetSymbolAddress((void**)&wvh, g_wvh);
    cudaGetSymbolAddress((void**)&wvl, g_wvl);
    cudaGetSymbolAddress((void**)&woh, g_woh);
    cudaGetSymbolAddress((void**)&wol, g_wol);
    cudaGetSymbolAddress((void**)&cth, g_cth);
    cudaGetSymbolAddress((void**)&ctl, g_ctl);
    cudaGetSymbolAddress((void**)&qah, g_qah);
    cudaGetSymbolAddress((void**)&qal, g_qal);
    cudaGetSymbolAddress((void**)&kch, g_kch);
    cudaGetSymbolAddress((void**)&kcl, g_kcl);
    cudaGetSymbolAddress((void**)&vch, g_vch);
    cudaGetSymbolAddress((void**)&vcl, g_vcl);
    cudaFuncSetAttribute(gemm_mma_kernel,
                         cudaFuncAttributeMaxDynamicSharedMemorySize, GEMM_SMEM);
    cudaFuncSetAttribute(attn_mma_kernel,
                         cudaFuncAttributeMaxDynamicSharedMemorySize, ATTN_SMEM);
    init_done = true;
  }

  const int M = B_ * T_;  // 2048

  // fp32 -> bf16 hi/lo conversions (x, weights)
  const int n4x = M * C_ / 4;
  const int n4q = C_ * C_ / 4;
  const int n4k = HKV * D_ * C_ / 4;
  cvt_kernel<<<(n4x + 255) / 256, 256>>>((const float4*)x,
      (__nv_bfloat162*)xh, (__nv_bfloat162*)xl, n4x);
  cvt_kernel<<<(n4q + 255) / 256, 256>>>((const float4*)Wq,
      (__nv_bfloat162*)wqh, (__nv_bfloat162*)wql, n4q);
  cvt_kernel<<<(n4k + 255) / 256, 256>>>((const float4*)Wk,
      (__nv_bfloat162*)wkh, (__nv_bfloat162*)wkl, n4k);
  cvt_kernel<<<(n4k + 255) / 256, 256>>>((const float4*)Wv,
      (__nv_bfloat162*)wvh, (__nv_bfloat162*)wvl, n4k);
  cvt_kernel<<<(n4q + 255) / 256, 256>>>((const float4*)Wo,
      (__nv_bfloat162*)woh, (__nv_bfloat162*)wol, n4q);

  // QKV projections (tensor cores)
  gemm_mma_kernel<<<dim3(C_ / 128, M / 128), 256, GEMM_SMEM>>>(
      xh, xl, wqh, wql, qb, M, C_, C_);
  gemm_mma_kernel<<<dim3((HKV * D_) / 128, M / 128), 256, GEMM_SMEM>>>(
      xh, xl, wkh, wkl, kb, M, HKV * D_, C_);
  gemm_mma_kernel<<<dim3((HKV * D_) / 128, M / 128), 256, GEMM_SMEM>>>(
      xh, xl, wvh, wvl, vb, M, HKV * D_, C_);

  // Fused rope + split + pack (fresh) and cache pack
  const int fpairs = M * HQ * 64 + 2 * M * HKV * 64;
  rope_pack_kernel<<<(fpairs + 255) / 256, 256>>>(qb, kb, vb, sp,
      (__nv_bfloat162*)qah, (__nv_bfloat162*)qal,
      (__nv_bfloat162*)kch, (__nv_bfloat162*)kcl,
      (__nv_bfloat162*)vch, (__nv_bfloat162*)vcl);
  const int npack = B_ * CT_ * HKV * (D_ / 4);
  pack_cache_kernel<<<(npack + 255) / 256, 256>>>(ck, cv, sp,
      (__nv_bfloat162*)kch, (__nv_bfloat162*)kcl,
      (__nv_bfloat162*)vch, (__nv_bfloat162*)vcl);

  // HMMA flash attention -> bf16 hi/lo ctx
  attn_mma_kernel<<<dim3(T_ / 32, HKV, B_), 256, ATTN_SMEM>>>(
      qah, qal, kch, kcl, vch, vcl, sp,
      (__nv_bfloat162*)cth, (__nv_bfloat162*)ctl);

  // Output projection
  gemm_mma_kernel<<<dim3(C_ / 128, M / 128), 256, GEMM_SMEM>>>(
      cth, ctl, woh, wol, out, M, C_, C_);
}

// round 12
// speedup vs baseline: 3.4263x; 1.0063x over previous
#include <cuda_runtime.h>
#include <cuda_bf16.h>
#include <cuda_fp16.h>
#include <cstdint>
#include <math.h>

// Problem constants
constexpr int B_   = 2;
constexpr int T_   = 1024;
constexpr int C_   = 4096;
constexpr int HQ   = 32;
constexpr int HKV  = 8;
constexpr int D_   = 128;
constexpr int G_   = 4;
constexpr int CT_  = 4096;
constexpr int NQKV = C_ + 2 * HKV * D_;  // 6144 fused QKV output width

// fp32 scratch: fused qkv output [M, 6144]
__device__ float g_qkv[(size_t)B_ * T_ * NQKV];

// bf16 hi/lo scratch
__device__ __nv_bfloat16 g_xh  [(size_t)B_ * T_ * C_];
__device__ __nv_bfloat16 g_xl  [(size_t)B_ * T_ * C_];
__device__ __nv_bfloat16 g_wqkvh[(size_t)NQKV * C_];
__device__ __nv_bfloat16 g_wqkvl[(size_t)NQKV * C_];
__device__ __nv_bfloat16 g_woh [(size_t)C_ * C_];
__device__ __nv_bfloat16 g_wol [(size_t)C_ * C_];
__device__ __nv_bfloat16 g_cth [(size_t)B_ * T_ * C_];
__device__ __nv_bfloat16 g_ctl [(size_t)B_ * T_ * C_];

// bf16 hi/lo attention operands
__device__ __nv_bfloat16 g_qah[(size_t)B_ * T_ * HQ * D_];
__device__ __nv_bfloat16 g_qal[(size_t)B_ * T_ * HQ * D_];
__device__ __nv_bfloat16 g_kch[(size_t)B_ * CT_ * HKV * D_];
__device__ __nv_bfloat16 g_kcl[(size_t)B_ * CT_ * HKV * D_];
__device__ __nv_bfloat16 g_vch[(size_t)B_ * CT_ * HKV * D_];
__device__ __nv_bfloat16 g_vcl[(size_t)B_ * CT_ * HKV * D_];

__device__ __forceinline__ uint32_t smem_u32(const void* p) {
  uint32_t a;
  asm("{ .reg .u64 t; cvta.to.shared.u64 t, %1; cvt.u32.u64 %0, t; }"
      : "=r"(a) : "l"(p));
  return a;
}

__device__ __forceinline__ void ldsm4(uint32_t* r, uint32_t addr) {
  asm volatile("ldmatrix.sync.aligned.m8n8.x4.shared.b16 {%0,%1,%2,%3}, [%4];"
               : "=r"(r[0]), "=r"(r[1]), "=r"(r[2]), "=r"(r[3]) : "r"(addr));
}

__device__ __forceinline__ void ldsm4t(uint32_t* r, uint32_t addr) {
  asm volatile("ldmatrix.sync.aligned.m8n8.x4.trans.shared.b16 {%0,%1,%2,%3}, [%4];"
               : "=r"(r[0]), "=r"(r[1]), "=r"(r[2]), "=r"(r[3]) : "r"(addr));
}

__device__ __forceinline__ void mma16816(float* d, const uint32_t* a,
                                         uint32_t b0, uint32_t b1) {
  asm volatile(
      "mma.sync.aligned.m16n8k16.row.col.f32.bf16.bf16.f32 "
      "{%0,%1,%2,%3},{%4,%5,%6,%7},{%8,%9},{%0,%1,%2,%3};"
      : "+f"(d[0]), "+f"(d[1]), "+f"(d[2]), "+f"(d[3])
      : "r"(a[0]), "r"(a[1]), "r"(a[2]), "r"(a[3]), "r"(b0), "r"(b1));
}

__device__ __forceinline__ void cp_async16(uint32_t dst, const void* src) {
  asm volatile("cp.async.cg.shared.global [%0], [%1], 16;"
               :: "r"(dst), "l"(src) : "memory");
}

__device__ __forceinline__ void split2(float a0, float a1, __nv_bfloat162& h,
                                       __nv_bfloat162& l) {
  h = __float22bfloat162_rn(make_float2(a0, a1));
  l = __float22bfloat162_rn(make_float2(a0 - __bfloat162float(h.x),
                                        a1 - __bfloat162float(h.y)));
}

// ---------------------------------------------------------------------------
// fp32 -> bf16 hi/lo split (elementwise)
// ---------------------------------------------------------------------------
__global__ void cvt_kernel(const float4* __restrict__ in,
                           __nv_bfloat162* __restrict__ hi,
                           __nv_bfloat162* __restrict__ lo, int n4) {
  int i = blockIdx.x * blockDim.x + threadIdx.x;
  if (i >= n4) return;
  float4 v = in[i];
  __nv_bfloat162 h0, l0, h1, l1;
  split2(v.x, v.y, h0, l0);
  split2(v.z, v.w, h1, l1);
  hi[2 * i] = h0; hi[2 * i + 1] = h1;
  lo[2 * i] = l0; lo[2 * i + 1] = l1;
}

// ---------------------------------------------------------------------------
// Fused rope + split + pack for fresh q/k/v, reading from the fused
// qkv buffer [M, 6144] (q at col 0, k at 4096, v at 5120).
// ---------------------------------------------------------------------------
__global__ void rope_pack_kernel(const float* __restrict__ qkv,
                                 const int* __restrict__ spp,
                                 __nv_bfloat162* __restrict__ qh,
                                 __nv_bfloat162* __restrict__ ql,
                                 __nv_bfloat162* __restrict__ kh,
                                 __nv_bfloat162* __restrict__ kl,
                                 __nv_bfloat162* __restrict__ vh,
                                 __nv_bfloat162* __restrict__ vl) {
  const int sp = *spp;
  const int M = B_ * T_;
  const int qpairs = M * HQ * 64;
  const int kpairs = M * HKV * 64;
  int idx = blockIdx.x * blockDim.x + threadIdx.x;

  if (idx < qpairs) {
    const int i = idx & 63, h = (idx >> 6) & 31, m = idx >> 11;
    const int t = m % T_;
    const float freq = __expf(-(float)i * (9.210340371976184f / 64.f));
    float s, c;
    sincosf((float)(sp + t) * freq, &s, &c);
    float2 x = *(const float2*)(qkv + (size_t)m * NQKV + h * D_ + 2 * i);
    float o0 = x.x * c - x.y * s, o1 = x.x * s + x.y * c;
    __nv_bfloat162 hh, ll;
    split2(o0, o1, hh, ll);
    qh[idx] = hh; ql[idx] = ll;
    return;
  }
  idx -= qpairs;
  if (idx < kpairs) {
    const int i = idx & 63, kv = (idx >> 6) & 7, m = idx >> 9;
    const int t = m % T_, b = m / T_;
    const float freq = __expf(-(float)i * (9.210340371976184f / 64.f));
    float s, c;
    sincosf((float)(sp + t) * freq, &s, &c);
    float2 x = *(const float2*)(qkv + (size_t)m * NQKV + C_ + kv * D_ + 2 * i);
    float o0 = x.x * c - x.y * s, o1 = x.x * s + x.y * c;
    __nv_bfloat162 hh, ll;
    split2(o0, o1, hh, ll);
    size_t dst = (((size_t)b * CT_ + sp + t) * HKV + kv) * 64 + i;
    kh[dst] = hh; kl[dst] = ll;
    return;
  }
  idx -= kpairs;
  if (idx >= kpairs) return;
  const int i = idx & 63, kv = (idx >> 6) & 7, m = idx >> 9;
  const int t = m % T_, b = m / T_;
  float2 x = *(const float2*)(qkv + (size_t)m * NQKV + C_ + HKV * D_ + kv * D_ + 2 * i);
  __nv_bfloat162 hh, ll;
  split2(x.x, x.y, hh, ll);
  size_t dst = (((size_t)b * CT_ + sp + t) * HKV + kv) * 64 + i;
  vh[dst] = hh; vl[dst] = ll;
}

// ---------------------------------------------------------------------------
// Pack cache K/V (s < sp only) -> bf16 hi/lo concat buffers.
// ---------------------------------------------------------------------------
__global__ void pack_cache_kernel(const float* __restrict__ ck,
                                  const float* __restrict__ cv,
                                  const int* __restrict__ spp,
                                  __nv_bfloat162* __restrict__ kh,
                                  __nv_bfloat162* __restrict__ kl,
                                  __nv_bfloat162* __restrict__ vh,
                                  __nv_bfloat162* __restrict__ vl) {
  const int sp = *spp;
  int idx = blockIdx.x * blockDim.x + threadIdx.x;  // over B*CT*HKV*(D/4)
  int d4 = idx & 31;
  int kv = (idx >> 5) & 7;
  int s  = (idx >> 8) & (CT_ - 1);
  int b  = idx >> 20;
  if (b >= B_ || s >= sp) return;

  size_t src = (((size_t)b * CT_ + s) * HKV + kv) * D_ + d4 * 4;
  size_t dst2 = ((((size_t)b * CT_ + s) * HKV + kv) * D_) / 2 + d4 * 2;

  float4 kx = *(const float4*)(ck + src);
  float4 vx = *(const float4*)(cv + src);
  __nv_bfloat162 h, l;
  split2(kx.x, kx.y, h, l); kh[dst2] = h; kl[dst2] = l;
  split2(kx.z, kx.w, h, l); kh[dst2 + 1] = h; kl[dst2 + 1] = l;
  split2(vx.x, vx.y, h, l); vh[dst2] = h; vl[dst2] = l;
  split2(vx.z, vx.w, h, l); vh[dst2 + 1] = h; vl[dst2 + 1] = l;
}

// ---------------------------------------------------------------------------
// Tensor-core GEMM (verified): C[M,N] = A[M,K]*B[N,K]^T, 3-term split.
// ---------------------------------------------------------------------------
__global__ void __launch_bounds__(256) gemm_mma_kernel(
    const __nv_bfloat16* __restrict__ Ah, const __nv_bfloat16* __restrict__ Al,
    const __nv_bfloat16* __restrict__ Bh, const __nv_bfloat16* __restrict__ Bl,
    float* __restrict__ C, int M, int N, int K) {
  extern __shared__ char sm[];
  const int tid = threadIdx.x, lane = tid & 31, wid = tid >> 5;
  const int bm = blockIdx.y << 7, bn = blockIdx.x << 7;
  const uint32_t sbase = smem_u32(sm);

  const int warp_m = wid >> 2;
  const int warp_n = wid & 3;

  const __nv_bfloat16* srcs[4] = {Ah, Al, Bh, Bl};

  auto issue = [&](int c, int buf) {
    const int k0 = c << 6;
    const int r = tid >> 1;
    const int s0 = (tid & 1) << 2;
#pragma unroll
    for (int m = 0; m < 4; m++) {
      const __nv_bfloat16* g =
          srcs[m] + (size_t)((m < 2 ? bm : bn) + r) * K + k0;
      uint32_t dstb = sbase + buf * 65536 + m * 16384 + r * 128;
      uint32_t rsw = (uint32_t)(r & 7) << 4;
#pragma unroll
      for (int i = 0; i < 4; i++) {
        int seg = s0 + i;
        cp_async16(dstb + ((uint32_t)(seg << 4) ^ rsw), g + seg * 8);
      }
    }
    asm volatile("cp.async.commit_group;" ::: "memory");
  };

  float acc[4][4][4];
#pragma unroll
  for (int i = 0; i < 4; i++)
#pragma unroll
    for (int j = 0; j < 4; j++)
#pragma unroll
      for (int t = 0; t < 4; t++) acc[i][j][t] = 0.f;

  const int l7 = lane & 7, m1b = (lane >> 3) & 1, m2b = lane >> 4;

  const int nch = K >> 6;
  issue(0, 0);
  for (int c = 0; c < nch; c++) {
    const int buf = c & 1;
    if (c + 1 < nch) {
      issue(c + 1, buf ^ 1);
      asm volatile("cp.async.wait_group 1;" ::: "memory");
    } else {
      asm volatile("cp.async.wait_group 0;" ::: "memory");
    }
    __syncthreads();

    const uint32_t bAh = sbase + buf * 65536;
    const uint32_t bAl = bAh + 16384;
    const uint32_t bBh = bAh + 32768;
    const uint32_t bBl = bAh + 49152;

#pragma unroll
    for (int kk = 0; kk < 4; kk++) {
      uint32_t ah[4][4], al[4][4], bh[2][4], bl[2][4];
#pragma unroll
      for (int i = 0; i < 4; i++) {
        int row = warp_m * 64 + i * 16 + l7 + m1b * 8;
        uint32_t bo = (uint32_t)(kk * 32 + m2b * 16) ^ ((uint32_t)(row & 7) << 4);
        uint32_t ro = (uint32_t)row * 128 + bo;
        ldsm4(ah[i], bAh + ro);
        ldsm4(al[i], bAl + ro);
      }
#pragma unroll
      for (int jp = 0; jp < 2; jp++) {
        int row = warp_n * 32 + jp * 16 + l7 + m2b * 8;
        uint32_t bo = (uint32_t)(kk * 32 + m1b * 16) ^ ((uint32_t)(row & 7) << 4);
        uint32_t ro = (uint32_t)row * 128 + bo;
        ldsm4(bh[jp], bBh + ro);
        ldsm4(bl[jp], bBl + ro);
      }
#pragma unroll
      for (int i = 0; i < 4; i++) {
#pragma unroll
        for (int j = 0; j < 4; j++) {
          uint32_t h0 = bh[j >> 1][(j & 1) * 2], h1 = bh[j >> 1][(j & 1) * 2 + 1];
          uint32_t l0 = bl[j >> 1][(j & 1) * 2], l1 = bl[j >> 1][(j & 1) * 2 + 1];
          mma16816(acc[i][j], ah[i], h0, h1);
          mma16816(acc[i][j], ah[i], l0, l1);
          mma16816(acc[i][j], al[i], h0, h1);
        }
      }
    }
    __syncthreads();
  }

  const int rq = lane >> 2, cq = (lane & 3) << 1;
#pragma unroll
  for (int i = 0; i < 4; i++) {
#pragma unroll
    for (int j = 0; j < 4; j++) {
      int row0 = bm + warp_m * 64 + i * 16 + rq;
      int col = bn + warp_n * 32 + j * 8 + cq;
      *(float2*)(C + (size_t)row0 * N + col) =
          make_float2(acc[i][j][0], acc[i][j][1]);
      *(float2*)(C + (size_t)(row0 + 8) * N + col) =
          make_float2(acc[i][j][2], acc[i][j][3]);
    }
  }
}

// ---------------------------------------------------------------------------
// HMMA flash attention (verified structure) + f16x2 exp softmax + bf16 out.
// Heavy-first t0 ordering: blockIdx.x reversed so long CTAs start first.
// ---------------------------------------------------------------------------
__global__ void __launch_bounds__(256) attn_mma_kernel(
    const __nv_bfloat16* __restrict__ qh_, const __nv_bfloat16* __restrict__ ql_,
    const __nv_bfloat16* __restrict__ kh_, const __nv_bfloat16* __restrict__ kl_,
    const __nv_bfloat16* __restrict__ vh_, const __nv_bfloat16* __restrict__ vl_,
    const int* __restrict__ spp, __nv_bfloat162* __restrict__ cth,
    __nv_bfloat162* __restrict__ ctl) {
  extern __shared__ __align__(1024) char sm[];
  const int sp = *spp;
  const int Stot = sp + T_;
  const int tid = threadIdx.x, lane = tid & 31, w = tid >> 5;
  const int t0 = (gridDim.x - 1 - blockIdx.x) << 5;  // heavy-first
  const int kv = blockIdx.y;
  const int b  = blockIdx.z;
  const uint32_t sb = smem_u32(sm);
  const uint32_t Qh = sb, Ql = sb + 32768;
  const uint32_t KV0 = sb + 65536;

#pragma unroll
  for (int it = 0; it < 16; it++) {
    int idx = it * 256 + tid;
    int mat = idx >> 11, rem = idx & 2047;
    int row = rem >> 4, seg = rem & 15;
    int t = t0 + (row >> 2), h = (kv << 2) + (row & 3);
    const __nv_bfloat16* src = (mat ? ql_ : qh_) +
        (((size_t)b * T_ + t) * HQ + h) * D_ + seg * 8;
    uint32_t dst = sb + mat * 32768 + (seg >> 3) * 16384 + (uint32_t)row * 128 +
        (((uint32_t)(seg & 7) << 4) ^ ((uint32_t)(row & 7) << 4));
    cp_async16(dst, src);
  }
  asm volatile("cp.async.commit_group;" ::: "memory");

  const __nv_bfloat16* kvsrc[4] = {kh_, kl_, vh_, vl_};
  auto issue_kv = [&](int c, int buf) {
    const uint32_t base = KV0 + (uint32_t)buf * 65536;
#pragma unroll
    for (int it = 0; it < 16; it++) {
      int idx = it * 256 + tid;
      int mat = idx >> 10, rem = idx & 1023;
      int row = rem >> 4, seg = rem & 15;
      int s = c * 64 + row;
      if (s > Stot - 1) s = Stot - 1;
      const __nv_bfloat16* g = kvsrc[mat] +
          (((size_t)b * CT_ + s) * HKV + kv) * D_ + seg * 8;
      uint32_t dst = base + mat * 16384 + (seg >> 3) * 8192 + (uint32_t)row * 128 +
          (((uint32_t)(seg & 7) << 4) ^ ((uint32_t)(row & 7) << 4));
      cp_async16(dst, g);
    }
    asm volatile("cp.async.commit_group;" ::: "memory");
  };

  float ctxf[16][4];
#pragma unroll
  for (int i = 0; i < 16; i++)
#pragma unroll
    for (int j = 0; j < 4; j++) ctxf[i][j] = 0.f;
  float m0 = -1e30f, m1 = -1e30f, l0 = 0.f, l1 = 0.f;

  const int wbase = w * 16;
  const int l7 = lane & 7, m1b = (lane >> 3) & 1, m2b = lane >> 4;
  const int r0 = wbase + (lane >> 2);
  const int lim0 = sp + t0 + (r0 >> 2);
  const int lim1 = sp + t0 + ((r0 + 8) >> 2);
  const float scale = 0.08838834764831845f;
  const float L2E = 1.4426950408889634f;

  const int nch = (sp + t0 + 31) / 64 + 1;
  issue_kv(0, 0);
  for (int c = 0; c < nch; c++) {
    const int buf = c & 1;
    if (c + 1 < nch) {
      issue_kv(c + 1, buf ^ 1);
      asm volatile("cp.async.wait_group 1;" ::: "memory");
    } else {
      asm volatile("cp.async.wait_group 0;" ::: "memory");
    }
    __syncthreads();

    const uint32_t Kh = KV0 + (uint32_t)buf * 65536, Kl = Kh + 16384;
    const uint32_t Vh = Kh + 32768, Vl = Kh + 49152;

    // ---- QK^T (3-term) ----
    float sc[8][4];
#pragma unroll
    for (int j = 0; j < 8; j++)
#pragma unroll
      for (int e = 0; e < 4; e++) sc[j][e] = 0.f;

#pragma unroll
    for (int kk = 0; kk < 8; kk++) {
      int arow = wbase + l7 + m1b * 8;
      uint32_t abo = ((uint32_t)((kk & 3) * 32 + m2b * 16)) ^
                     ((uint32_t)(arow & 7) << 4);
      uint32_t aoff = (uint32_t)(kk >> 2) * 16384 + (uint32_t)arow * 128 + abo;
      uint32_t ah[4], al[4];
      ldsm4(ah, Qh + aoff);
      ldsm4(al, Ql + aoff);
#pragma unroll
      for (int jp = 0; jp < 4; jp++) {
        int brow = jp * 16 + l7 + m2b * 8;
        uint32_t bbo = ((uint32_t)((kk & 3) * 32 + m1b * 16)) ^
                       ((uint32_t)(brow & 7) << 4);
        uint32_t boff = (uint32_t)(kk >> 2) * 8192 + (uint32_t)brow * 128 + bbo;
        uint32_t bh[4], bl[4];
        ldsm4(bh, Kh + boff);
        ldsm4(bl, Kl + boff);
        mma16816(sc[jp * 2], ah, bh[0], bh[1]);
        mma16816(sc[jp * 2], ah, bl[0], bl[1]);
        mma16816(sc[jp * 2], al, bh[0], bh[1]);
        mma16816(sc[jp * 2 + 1], ah, bh[2], bh[3]);
        mma16816(sc[jp * 2 + 1], ah, bl[2], bl[3]);
        mma16816(sc[jp * 2 + 1], al, bh[2], bh[3]);
      }
    }

    // ---- mask + online softmax ----
    const int kbase = c * 64;
    float cm0 = -1e30f, cm1 = -1e30f;
#pragma unroll
    for (int j = 0; j < 8; j++) {
#pragma unroll
      for (int e = 0; e < 2; e++) {
        int key = kbase + j * 8 + 2 * (lane & 3) + e;
        float v0 = sc[j][e] * scale;
        float v1 = sc[j][2 + e] * scale;
        if (key > lim0) v0 = -1e30f;
        if (key > lim1) v1 = -1e30f;
        sc[j][e] = v0; sc[j][2 + e] = v1;
        cm0 = fmaxf(cm0, v0); cm1 = fmaxf(cm1, v1);
      }
    }
    cm0 = fmaxf(cm0, __shfl_xor_sync(0xffffffffu, cm0, 1));
    cm0 = fmaxf(cm0, __shfl_xor_sync(0xffffffffu, cm0, 2));
    cm1 = fmaxf(cm1, __shfl_xor_sync(0xffffffffu, cm1, 1));
    cm1 = fmaxf(cm1, __shfl_xor_sync(0xffffffffu, cm1, 2));
    float mn0 = fmaxf(m0, cm0), mn1 = fmaxf(m1, cm1);
    float s0f = __expf(m0 - mn0), s1f = __expf(m1 - mn1);
    m0 = mn0; m1 = mn1;
    const float m0L = m0 * L2E, m1L = m1 * L2E;

    float ps0 = 0.f, ps1 = 0.f;
    uint32_t pkh[8][2], pkl[8][2];
#pragma unroll
    for (int j = 0; j < 8; j++) {
      float y0 = fmaf(sc[j][0], L2E, -m0L), y1 = fmaf(sc[j][1], L2E, -m0L);
      float y2 = fmaf(sc[j][2], L2E, -m1L), y3 = fmaf(sc[j][3], L2E, -m1L);
      float2 p01 = __half22float2(h2exp2(__floats2half2_rn(y0, y1)));
      float2 p23 = __half22float2(h2exp2(__floats2half2_rn(y2, y3)));
      float p0 = p01.x, p1 = p01.y, p2 = p23.x, p3 = p23.y;
      ps0 += p0 + p1; ps1 += p2 + p3;
      __nv_bfloat162 h, l;
      split2(p0, p1, h, l);
      pkh[j][0] = *(uint32_t*)&h; pkl[j][0] = *(uint32_t*)&l;
      split2(p2, p3, h, l);
      pkh[j][1] = *(uint32_t*)&h; pkl[j][1] = *(uint32_t*)&l;
    }
    ps0 += __shfl_xor_sync(0xffffffffu, ps0, 1);
    ps0 += __shfl_xor_sync(0xffffffffu, ps0, 2);
    ps1 += __shfl_xor_sync(0xffffffffu, ps1, 1);
    ps1 += __shfl_xor_sync(0xffffffffu, ps1, 2);
    l0 = l0 * s0f + ps0;
    l1 = l1 * s1f + ps1;
#pragma unroll
    for (int nt = 0; nt < 16; nt++) {
      ctxf[nt][0] *= s0f; ctxf[nt][1] *= s0f;
      ctxf[nt][2] *= s1f; ctxf[nt][3] *= s1f;
    }

    // ---- P·V (3-term) ----
#pragma unroll
    for (int k0 = 0; k0 < 4; k0++) {
      uint32_t aH[4] = {pkh[2 * k0][0], pkh[2 * k0][1],
                        pkh[2 * k0 + 1][0], pkh[2 * k0 + 1][1]};
      uint32_t aL[4] = {pkl[2 * k0][0], pkl[2 * k0][1],
                        pkl[2 * k0 + 1][0], pkl[2 * k0 + 1][1]};
      const int mI = lane >> 3, iI = lane & 7;
      const int keyr = k0 * 16 + iI + (mI & 1) * 8;
#pragma unroll
      for (int nn = 0; nn < 8; nn++) {
        int dstart = nn * 16 + (mI >> 1) * 8;
        uint32_t voff = (uint32_t)(dstart >> 6) * 8192 + (uint32_t)keyr * 128 +
            (((uint32_t)(dstart & 63) * 2) ^ ((uint32_t)(keyr & 7) << 4));
        uint32_t bh[4], bl[4];
        ldsm4t(bh, Vh + voff);
        ldsm4t(bl, Vl + voff);
        mma16816(ctxf[2 * nn], aH, bh[0], bh[1]);
        mma16816(ctxf[2 * nn], aH, bl[0], bl[1]);
        mma16816(ctxf[2 * nn], aL, bh[0], bh[1]);
        mma16816(ctxf[2 * nn + 1], aH, bh[2], bh[3]);
        mma16816(ctxf[2 * nn + 1], aH, bl[2], bl[3]);
        mma16816(ctxf[2 * nn + 1], aL, bh[2], bh[3]);
      }
    }
    __syncthreads();
  }

  // ---- epilogue: write bf16 hi/lo ctx directly ----
  const float il0 = 1.f / l0, il1 = 1.f / l1;
  const int tq0 = t0 + (r0 >> 2), tq1 = t0 + ((r0 + 8) >> 2);
  const int h = (kv << 2) + (r0 & 3);
  size_t o0 = (((size_t)b * T_ + tq0) * HQ + h) * (size_t)D_;
  size_t o1 = (((size_t)b * T_ + tq1) * HQ + h) * (size_t)D_;
#pragma unroll
  for (int nt = 0; nt < 16; nt++) {
    int d = nt * 8 + 2 * (lane & 3);
    __nv_bfloat162 hh, ll;
    split2(ctxf[nt][0] * il0, ctxf[nt][1] * il0, hh, ll);
    cth[(o0 + d) >> 1] = hh; ctl[(o0 + d) >> 1] = ll;
    split2(ctxf[nt][2] * il1, ctxf[nt][3] * il1, hh, ll);
    cth[(o1 + d) >> 1] = hh; ctl[(o1 + d) >> 1] = ll;
  }
}

// ---------------------------------------------------------------------------
// kernel_launch
// ---------------------------------------------------------------------------
extern "C" void kernel_launch(void* const* d_in, const int* in_sizes, int n_in,
                              void* d_out, int out_size) {
  const float* x  = (const float*)d_in[0];
  const int*   sp = (const int*)  d_in[1];
  const float* ck = (const float*)d_in[2];
  const float* cv = (const float*)d_in[3];
  const float* Wq = (const float*)d_in[4];
  const float* Wk = (const float*)d_in[5];
  const float* Wv = (const float*)d_in[6];
  const float* Wo = (const float*)d_in[7];
  float* out = (float*)d_out;

  constexpr int GEMM_SMEM = 131072;
  constexpr int ATTN_SMEM = 196608;

  static float *qkvb;
  static __nv_bfloat16 *xh, *xl, *wqkvh, *wqkvl, *woh, *wol,
      *cth, *ctl, *qah, *qal, *kch, *kcl, *vch, *vcl;
  static bool init_done = false;
  if (!init_done) {
    cudaGetSymbolAddress((void**)&qkvb, g_qkv);
    cudaGetSymbolAddress((void**)&xh, g_xh);
    cudaGetSymbolAddress((void**)&xl, g_xl);
    cudaGetSymbolAddress((void**)&wqkvh, g_wqkvh);
    cudaGetSymbolAddress((void**)&wqkvl, g_wqkvl);
    cudaGetSymbolAddress((void**)&woh, g_woh);
    cudaGetSymbolAddress((void**)&wol, g_wol);
    cudaGetSymbolAddress((void**)&cth, g_cth);
    cudaGetSymbolAddress((void**)&ctl, g_ctl);
    cudaGetSymbolAddress((void**)&qah, g_qah);
    cudaGetSymbolAddress((void**)&qal, g_qal);
    cudaGetSymbolAddress((void**)&kch, g_kch);
    cudaGetSymbolAddress((void**)&kcl, g_kcl);
    cudaGetSymbolAddress((void**)&vch, g_vch);
    cudaGetSymbolAddress((void**)&vcl, g_vcl);
    cudaFuncSetAttribute(gemm_mma_kernel,
                         cudaFuncAttributeMaxDynamicSharedMemorySize, GEMM_SMEM);
    cudaFuncSetAttribute(attn_mma_kernel,
                         cudaFuncAttributeMaxDynamicSharedMemorySize, ATTN_SMEM);
    init_done = true;
  }

  const int M = B_ * T_;  // 2048

  // fp32 -> bf16 hi/lo conversions: x, fused W_qkv (rows 0-4095 Wq,
  // 4096-5119 Wk, 5120-6143 Wv), Wo
  const int n4x = M * C_ / 4;
  const int n4q = C_ * C_ / 4;
  const int n4k = HKV * D_ * C_ / 4;
  const size_t kofs = (size_t)C_ * C_;          // elements
  const size_t vofs = kofs + (size_t)HKV * D_ * C_;
  cvt_kernel<<<(n4x + 255) / 256, 256>>>((const float4*)x,
      (__nv_bfloat162*)xh, (__nv_bfloat162*)xl, n4x);
  cvt_kernel<<<(n4q + 255) / 256, 256>>>((const float4*)Wq,
      (__nv_bfloat162*)wqkvh, (__nv_bfloat162*)wqkvl, n4q);
  cvt_kernel<<<(n4k + 255) / 256, 256>>>((const float4*)Wk,
      (__nv_bfloat162*)(wqkvh + kofs), (__nv_bfloat162*)(wqkvl + kofs), n4k);
  cvt_kernel<<<(n4k + 255) / 256, 256>>>((const float4*)Wv,
      (__nv_bfloat162*)(wqkvh + vofs), (__nv_bfloat162*)(wqkvl + vofs), n4k);
  cvt_kernel<<<(n4q + 255) / 256, 256>>>((const float4*)Wo,
      (__nv_bfloat162*)woh, (__nv_bfloat162*)wol, n4q);

  // Fused QKV projection: C[M, 6144]
  gemm_mma_kernel<<<dim3(NQKV / 128, M / 128), 256, GEMM_SMEM>>>(
      xh, xl, wqkvh, wqkvl, qkvb, M, NQKV, C_);

  // Fused rope + split + pack (fresh) and cache pack
  const int fpairs = M * HQ * 64 + 2 * M * HKV * 64;
  rope_pack_kernel<<<(fpairs + 255) / 256, 256>>>(qkvb, sp,
      (__nv_bfloat162*)qah, (__nv_bfloat162*)qal,
      (__nv_bfloat162*)kch, (__nv_bfloat162*)kcl,
      (__nv_bfloat162*)vch, (__nv_bfloat162*)vcl);
  const int npack = B_ * CT_ * HKV * (D_ / 4);
  pack_cache_kernel<<<(npack + 255) / 256, 256>>>(ck, cv, sp,
      (__nv_bfloat162*)kch, (__nv_bfloat162*)kcl,
      (__nv_bfloat162*)vch, (__nv_bfloat162*)vcl);

  // HMMA flash attention -> bf16 hi/lo ctx
  attn_mma_kernel<<<dim3(T_ / 32, HKV, B_), 256, ATTN_SMEM>>>(
      qah, qal, kch, kcl, vch, vcl, sp,
      (__nv_bfloat162*)cth, (__nv_bfloat162*)ctl);

  // Output projection
  gemm_mma_kernel<<<dim3(C_ / 128, M / 128), 256, GEMM_SMEM>>>(
      cth, ctl, woh, wol, out, M, C_, C_);
}